// round 10
// baseline (speedup 1.0000x reference)
#include <cuda_runtime.h>
#include <math.h>

#define Bq    4
#define Sq    1024
#define Cdim  256
#define INNERq 512
#define NHq   8
#define DHq   64

// ---------------- scratch (static __device__, no allocation) ----------------
__device__ float g_xm[Bq*Sq*INNERq];
__device__ float g_z [Bq*Sq*INNERq];
__device__ float g_xa[Bq*Sq*INNERq];
__device__ float g_q [Bq*Sq*INNERq];
__device__ float g_k [Bq*Sq*INNERq];
__device__ float g_v [Bq*Sq*INNERq];
__device__ float g_ig[Bq*NHq*Sq];
__device__ float g_fg[Bq*NHq*Sq];
__device__ float g_lc[Bq*NHq*Sq];
__device__ float g_h [Bq*Sq*INNERq];

// ---------------- NT GEMM: C[m,n] = sum_k A[m,k]*B[n,k], k-tile 32 ----------------
template<int MODE>
__global__ __launch_bounds__(256) void gemm_nt(
    const float* __restrict__ Aext, const float* __restrict__ Bm,
    float* __restrict__ outext, int Kd)
{
    __shared__ float As[32][65];
    __shared__ float Bs[32][65];
    const float* A = (MODE == 0) ? Aext : g_h;
    int tid = threadIdx.x;
    int m0 = blockIdx.y * 64, n0 = blockIdx.x * 64;
    int ty = tid >> 4, tx = tid & 15;
    int lr  = tid >> 2;          // 0..63
    int lc8 = (tid & 3) << 3;    // 0,8,16,24
    float acc[4][4] = {};
    const float* Ap = A  + (size_t)(m0 + lr) * Kd + lc8;
    const float* Bp = Bm + (size_t)(n0 + lr) * Kd + lc8;
    for (int k0 = 0; k0 < Kd; k0 += 32) {
        float4 a0 = *(const float4*)(Ap + k0);
        float4 a1 = *(const float4*)(Ap + k0 + 4);
        float4 b0 = *(const float4*)(Bp + k0);
        float4 b1 = *(const float4*)(Bp + k0 + 4);
        As[lc8+0][lr] = a0.x; As[lc8+1][lr] = a0.y; As[lc8+2][lr] = a0.z; As[lc8+3][lr] = a0.w;
        As[lc8+4][lr] = a1.x; As[lc8+5][lr] = a1.y; As[lc8+6][lr] = a1.z; As[lc8+7][lr] = a1.w;
        Bs[lc8+0][lr] = b0.x; Bs[lc8+1][lr] = b0.y; Bs[lc8+2][lr] = b0.z; Bs[lc8+3][lr] = b0.w;
        Bs[lc8+4][lr] = b1.x; Bs[lc8+5][lr] = b1.y; Bs[lc8+6][lr] = b1.z; Bs[lc8+7][lr] = b1.w;
        __syncthreads();
        #pragma unroll
        for (int kk = 0; kk < 32; kk++) {
            float a[4], b[4];
            #pragma unroll
            for (int i = 0; i < 4; i++) { a[i] = As[kk][ty*4+i]; b[i] = Bs[kk][tx*4+i]; }
            #pragma unroll
            for (int i = 0; i < 4; i++)
                #pragma unroll
                for (int j = 0; j < 4; j++) acc[i][j] += a[i] * b[j];
        }
        __syncthreads();
    }
    #pragma unroll
    for (int i = 0; i < 4; i++) {
        int m = m0 + ty*4 + i;
        #pragma unroll
        for (int j = 0; j < 4; j++) {
            int n = n0 + tx*4 + j;
            if (MODE == 0) {
                if (n < INNERq) g_xm[(size_t)m * INNERq + n] = acc[i][j];
                else            g_z [(size_t)m * INNERq + (n - INNERq)] = acc[i][j];
            } else {
                outext[(size_t)m * Cdim + n] = acc[i][j];
            }
        }
    }
}

// ---------------- conv + silu + per-block qkv (gates moved out) ----------------
__global__ __launch_bounds__(128) void fused_conv_qkv(
    const float* __restrict__ conv_w, const float* __restrict__ conv_b,
    const float* __restrict__ Wq, const float* __restrict__ Wk, const float* __restrict__ Wv)
{
    int bs = blockIdx.x;
    int b = bs >> 10;
    int s = bs & 1023;
    int t = threadIdx.x;
    size_t rowbase = (size_t)bs * INNERq;

    float xm4[4], xa4[4];
    #pragma unroll
    for (int j = 0; j < 4; j++) {
        int c = t*4 + j;
        float a = conv_b[c];
        #pragma unroll
        for (int kk = 0; kk < 4; kk++) {
            int sp = s - 3 + kk;
            if (sp >= 0) a += g_xm[((size_t)(b*Sq + sp)) * INNERq + c] * conv_w[c*4 + kk];
        }
        float sg = 1.f / (1.f + __expf(-a));
        xa4[j] = a * sg;
        g_xa[rowbase + c] = xa4[j];
        xm4[j] = g_xm[rowbase + c];
    }

    float q4[4], k4[4], v4[4];
    #pragma unroll
    for (int o = 0; o < 4; o++) {
        float aq = 0.f, ak = 0.f, av = 0.f;
        #pragma unroll
        for (int d = 0; d < 4; d++) {
            aq += Wq[t*16 + o*4 + d] * xa4[d];
            ak += Wk[t*16 + o*4 + d] * xa4[d];
            av += Wv[t*16 + o*4 + d] * xm4[d];
        }
        q4[o] = aq; k4[o] = ak; v4[o] = av;
    }
    *(float4*)&g_q[rowbase + t*4] = make_float4(q4[0], q4[1], q4[2], q4[3]);
    *(float4*)&g_k[rowbase + t*4] = make_float4(k4[0], k4[1], k4[2], k4[3]);
    *(float4*)&g_v[rowbase + t*4] = make_float4(v4[0], v4[1], v4[2], v4[3]);
}

// ---------------- gates as GEMM: [4096,16] = [q|k|v](4096x1536) @ W^T ----------------
// 32 blocks x 128 rows; 256 threads = (row r, k-half). W k-tiles in smem (broadcast reads).
// Wt row stride 132 floats (528B = 33*16) keeps every float4 access 16B-aligned.
__global__ __launch_bounds__(256) void gates_kernel(
    const float* __restrict__ W_i, const float* __restrict__ b_i,
    const float* __restrict__ W_f, const float* __restrict__ b_f)
{
    __shared__ float Wt[16][132];      // 16 gates x 128 k (+4 pad, 16B-aligned rows)
    __shared__ float red[128][17];     // cross-half reduction staging
    int t = threadIdx.x;
    int r = t & 127;
    int half = t >> 7;
    int row = blockIdx.x * 128 + r;
    int b = row >> 10, s = row & 1023;

    float acc[16];
    #pragma unroll
    for (int g = 0; g < 16; g++) acc[g] = 0.f;

    #pragma unroll
    for (int seg = 0; seg < 3; seg++) {
        const float* src = (seg == 0) ? g_q : (seg == 1) ? g_k : g_v;
        const float* base = src + (size_t)row * INNERq;
        for (int k0 = 0; k0 < 512; k0 += 128) {
            // cooperative W tile load: 512 float4, 256 threads -> 2 each
            #pragma unroll
            for (int i = 0; i < 2; i++) {
                int e = t + 256*i;
                int g = e >> 5;
                int c4 = (e & 31) << 2;
                const float* Wsrc = (g < 8) ? (W_i + g*1536) : (W_f + (g-8)*1536);
                *(float4*)&Wt[g][c4] = *(const float4*)&Wsrc[seg*512 + k0 + c4];
            }
            __syncthreads();
            int kbeg = half * 64;
            #pragma unroll 4
            for (int k4 = kbeg; k4 < kbeg + 64; k4 += 4) {
                float4 a = *(const float4*)&base[k0 + k4];
                #pragma unroll
                for (int g = 0; g < 16; g++) {
                    float4 w = *(const float4*)&Wt[g][k4];
                    acc[g] += a.x*w.x + a.y*w.y + a.z*w.z + a.w*w.w;
                }
            }
            __syncthreads();
        }
    }
    // combine halves via smem
    if (half == 1) {
        #pragma unroll
        for (int g = 0; g < 16; g++) red[r][g] = acc[g];
    }
    __syncthreads();
    if (half == 0) {
        #pragma unroll
        for (int h = 0; h < 8; h++) {
            float ig = acc[h]   + red[r][h]   + b_i[h];
            float fg = acc[8+h] + red[r][8+h] + b_f[h];
            g_ig[(size_t)(b*NHq + h) * Sq + s] = ig;
            g_fg[(size_t)(b*NHq + h) * Sq + s] = fg;
        }
    }
}

// ---------------- log-sigmoid + inclusive cumsum over S per (b,h) ----------------
__global__ __launch_bounds__(1024) void scan_kernel()
{
    int bh = blockIdx.x;
    int s = threadIdx.x;
    float x = g_fg[(size_t)bh * Sq + s];
    float lf = fminf(x, 0.f) - log1pf(expf(-fabsf(x)));
    __shared__ float sc[Sq];
    sc[s] = lf;
    __syncthreads();
    for (int off = 1; off < Sq; off <<= 1) {
        float tv = (s >= off) ? sc[s - off] : 0.f;
        __syncthreads();
        sc[s] += tv;
        __syncthreads();
    }
    g_lc[(size_t)bh * Sq + s] = sc[s];
}

// ---------------- streaming mLSTM attention v4b: 64x64 tiles, 4x4 micro, 4 blk/SM ----------------
#define ATT_STRIDE 68
#define ATT_SMEM_FLOATS (3*64*ATT_STRIDE + 7*64)
#define ATT_SMEM_BYTES  (ATT_SMEM_FLOATS*4)

__global__ __launch_bounds__(256, 4) void attn_kernel(
    const float* __restrict__ norm_w, const float* __restrict__ skipw)
{
    extern __shared__ float sm[];
    float* Qt = sm;                       // [64][68] Q^T (reused as O)
    float* KV = Qt + 64*ATT_STRIDE;       // [64][68] K^T then V
    float* Pt = KV + 64*ATT_STRIDE;       // [64][68] P row-major
    float* pm       = Pt + 64*ATT_STRIDE;
    float* ej       = pm + 64;
    float* m_row    = ej + 64;
    float* sc_row   = m_row + 64;
    float* Ei_row   = sc_row + 64;
    float* ssum_row = Ei_row + 64;
    float* lci_row  = ssum_row + 64;

    int xblk = blockIdx.x;
    int it = 15 - (xblk >> 5);
    int bh = xblk & 31;
    int b = bh >> 3, h = bh & 7;
    int i0 = it * 64;
    int t = threadIdx.x;
    int tx = t & 15, ty = t >> 4;

    #pragma unroll
    for (int e4 = 0; e4 < 4; e4++) {
        int e = t + 256 * e4;
        int row = e >> 4, c4 = (e & 15) << 2;
        float4 qv = *(const float4*)&g_q[((size_t)(b*Sq + i0 + row)) * INNERq + h*DHq + c4];
        Qt[(c4+0)*ATT_STRIDE + row] = qv.x;
        Qt[(c4+1)*ATT_STRIDE + row] = qv.y;
        Qt[(c4+2)*ATT_STRIDE + row] = qv.z;
        Qt[(c4+3)*ATT_STRIDE + row] = qv.w;
    }
    if (t < 64) {
        lci_row[t]  = g_lc[(size_t)bh*Sq + i0 + t];
        m_row[t]    = -3.4e38f;
        ssum_row[t] = 0.f;
    }

    float acc[4][4];
    #pragma unroll
    for (int a = 0; a < 4; a++)
        #pragma unroll
        for (int d = 0; d < 4; d++) acc[a][d] = 0.f;

    for (int jt = 0; jt <= it; jt++) {
        int j0 = jt * 64;
        __syncthreads();

        #pragma unroll
        for (int e4 = 0; e4 < 4; e4++) {
            int e = t + 256*e4;
            int row = e >> 4, c4 = (e & 15) << 2;
            float4 kv = *(const float4*)&g_k[((size_t)(b*Sq + j0 + row)) * INNERq + h*DHq + c4];
            KV[(c4+0)*ATT_STRIDE + row] = kv.x*0.125f;
            KV[(c4+1)*ATT_STRIDE + row] = kv.y*0.125f;
            KV[(c4+2)*ATT_STRIDE + row] = kv.z*0.125f;
            KV[(c4+3)*ATT_STRIDE + row] = kv.w*0.125f;
        }
        if (t < 32) {
            int l = t;
            size_t gbase = (size_t)bh*Sq + j0;
            float a0 = g_ig[gbase + l]      - g_lc[gbase + l];
            float a1 = g_ig[gbase + 32 + l] - g_lc[gbase + 32 + l];
            float p0 = a0;
            #pragma unroll
            for (int off = 1; off < 32; off <<= 1) {
                float u = __shfl_up_sync(0xffffffffu, p0, off);
                if (l >= off) p0 = fmaxf(p0, u);
            }
            float max0 = __shfl_sync(0xffffffffu, p0, 31);
            float p1 = a1;
            #pragma unroll
            for (int off = 1; off < 32; off <<= 1) {
                float u = __shfl_up_sync(0xffffffffu, p1, off);
                if (l >= off) p1 = fmaxf(p1, u);
            }
            p1 = fmaxf(p1, max0);
            float pmAll = __shfl_sync(0xffffffffu, p1, 31);
            pm[l]      = p0;
            pm[32 + l] = p1;
            ej[l]      = __expf(a0 - pmAll);
            ej[32 + l] = __expf(a1 - pmAll);
            __syncwarp();
            #pragma unroll
            for (int half = 0; half < 2; half++) {
                int r = l + 32*half;
                int jm = i0 + r - j0 + 1;
                jm = jm > 64 ? 64 : jm;
                float mo = m_row[r];
                float rowmax = lci_row[r] + pm[jm-1];
                float mnew = fmaxf(mo, rowmax);
                float sc = __expf(mo - mnew);
                sc_row[r] = sc;
                Ei_row[r] = __expf(lci_row[r] + pmAll - mnew);
                m_row[r]  = mnew;
                ssum_row[r] *= sc;
            }
        }
        __syncthreads();

        #pragma unroll
        for (int a = 0; a < 4; a++) {
            float sc = sc_row[4*ty + a];
            #pragma unroll
            for (int d = 0; d < 4; d++) acc[a][d] *= sc;
        }

        float s[4][4];
        #pragma unroll
        for (int a = 0; a < 4; a++)
            #pragma unroll
            for (int c = 0; c < 4; c++) s[a][c] = 0.f;
        #pragma unroll 8
        for (int kk = 0; kk < 64; kk++) {
            float4 aq = *(const float4*)&Qt[kk*ATT_STRIDE + 4*ty];
            float4 bk = *(const float4*)&KV[kk*ATT_STRIDE + 4*tx];
            s[0][0] += aq.x*bk.x; s[0][1] += aq.x*bk.y; s[0][2] += aq.x*bk.z; s[0][3] += aq.x*bk.w;
            s[1][0] += aq.y*bk.x; s[1][1] += aq.y*bk.y; s[1][2] += aq.y*bk.z; s[1][3] += aq.y*bk.w;
            s[2][0] += aq.z*bk.x; s[2][1] += aq.z*bk.y; s[2][2] += aq.z*bk.z; s[2][3] += aq.z*bk.w;
            s[3][0] += aq.w*bk.x; s[3][1] += aq.w*bk.y; s[3][2] += aq.w*bk.z; s[3][3] += aq.w*bk.w;
        }
        {
            float e0 = ej[4*tx], e1 = ej[4*tx+1], e2 = ej[4*tx+2], e3 = ej[4*tx+3];
            bool diag = (jt == it);
            int jg = j0 + 4*tx;
            #pragma unroll
            for (int a = 0; a < 4; a++) {
                int rr = 4*ty + a;
                float Ei = Ei_row[rr];
                float p0 = s[a][0]*Ei*e0;
                float p1 = s[a][1]*Ei*e1;
                float p2 = s[a][2]*Ei*e2;
                float p3 = s[a][3]*Ei*e3;
                if (diag) {
                    int ig = i0 + rr;
                    if (jg     > ig) p0 = 0.f;
                    if (jg + 1 > ig) p1 = 0.f;
                    if (jg + 2 > ig) p2 = 0.f;
                    if (jg + 3 > ig) p3 = 0.f;
                }
                *(float4*)&Pt[rr*ATT_STRIDE + 4*tx] = make_float4(p0, p1, p2, p3);
                float part = (p0 + p1) + (p2 + p3);
                part += __shfl_xor_sync(0xffffffffu, part, 1);
                part += __shfl_xor_sync(0xffffffffu, part, 2);
                part += __shfl_xor_sync(0xffffffffu, part, 4);
                part += __shfl_xor_sync(0xffffffffu, part, 8);
                if (tx == 0) ssum_row[rr] += part;
            }
        }
        __syncthreads();

        #pragma unroll
        for (int e4 = 0; e4 < 4; e4++) {
            int e = t + 256*e4;
            int row = e >> 4, c4 = (e & 15) << 2;
            *(float4*)&KV[row*ATT_STRIDE + c4] =
                *(const float4*)&g_v[((size_t)(b*Sq + j0 + row)) * INNERq + h*DHq + c4];
        }
        __syncthreads();

        #pragma unroll 4
        for (int jj = 0; jj < 64; jj += 4) {
            float4 pa0 = *(const float4*)&Pt[(4*ty+0)*ATT_STRIDE + jj];
            float4 pa1 = *(const float4*)&Pt[(4*ty+1)*ATT_STRIDE + jj];
            float4 pa2 = *(const float4*)&Pt[(4*ty+2)*ATT_STRIDE + jj];
            float4 pa3 = *(const float4*)&Pt[(4*ty+3)*ATT_STRIDE + jj];
            float4 vb0 = *(const float4*)&KV[(jj+0)*ATT_STRIDE + 4*tx];
            float4 vb1 = *(const float4*)&KV[(jj+1)*ATT_STRIDE + 4*tx];
            float4 vb2 = *(const float4*)&KV[(jj+2)*ATT_STRIDE + 4*tx];
            float4 vb3 = *(const float4*)&KV[(jj+3)*ATT_STRIDE + 4*tx];
            acc[0][0] += pa0.x*vb0.x + pa0.y*vb1.x + pa0.z*vb2.x + pa0.w*vb3.x;
            acc[0][1] += pa0.x*vb0.y + pa0.y*vb1.y + pa0.z*vb2.y + pa0.w*vb3.y;
            acc[0][2] += pa0.x*vb0.z + pa0.y*vb1.z + pa0.z*vb2.z + pa0.w*vb3.z;
            acc[0][3] += pa0.x*vb0.w + pa0.y*vb1.w + pa0.z*vb2.w + pa0.w*vb3.w;
            acc[1][0] += pa1.x*vb0.x + pa1.y*vb1.x + pa1.z*vb2.x + pa1.w*vb3.x;
            acc[1][1] += pa1.x*vb0.y + pa1.y*vb1.y + pa1.z*vb2.y + pa1.w*vb3.y;
            acc[1][2] += pa1.x*vb0.z + pa1.y*vb1.z + pa1.z*vb2.z + pa1.w*vb3.z;
            acc[1][3] += pa1.x*vb0.w + pa1.y*vb1.w + pa1.z*vb2.w + pa1.w*vb3.w;
            acc[2][0] += pa2.x*vb0.x + pa2.y*vb1.x + pa2.z*vb2.x + pa2.w*vb3.x;
            acc[2][1] += pa2.x*vb0.y + pa2.y*vb1.y + pa2.z*vb2.y + pa2.w*vb3.y;
            acc[2][2] += pa2.x*vb0.z + pa2.y*vb1.z + pa2.z*vb2.z + pa2.w*vb3.z;
            acc[2][3] += pa2.x*vb0.w + pa2.y*vb1.w + pa2.z*vb2.w + pa2.w*vb3.w;
            acc[3][0] += pa3.x*vb0.x + pa3.y*vb1.x + pa3.z*vb2.x + pa3.w*vb3.x;
            acc[3][1] += pa3.x*vb0.y + pa3.y*vb1.y + pa3.z*vb2.y + pa3.w*vb3.y;
            acc[3][2] += pa3.x*vb0.z + pa3.y*vb1.z + pa3.z*vb2.z + pa3.w*vb3.z;
            acc[3][3] += pa3.x*vb0.w + pa3.y*vb1.w + pa3.z*vb2.w + pa3.w*vb3.w;
        }
    }

    #pragma unroll
    for (int a = 0; a < 4; a++)
        *(float4*)&Qt[(4*ty + a)*ATT_STRIDE + 4*tx] =
            make_float4(acc[a][0], acc[a][1], acc[a][2], acc[a][3]);
    __syncthreads();

    {
        int row = t >> 2, qd = t & 3;
        int i = i0 + row;
        float m    = m_row[row];
        float ssum = ssum_row[row];
        float denom = fmaxf(fabsf(ssum), __expf(-m)) + 1e-6f;
        float inv = 1.f / denom;
        float o[16];
        #pragma unroll
        for (int k4 = 0; k4 < 4; k4++) {
            float4 v = *(const float4*)&Qt[row*ATT_STRIDE + qd*16 + k4*4];
            o[k4*4+0] = v.x*inv; o[k4*4+1] = v.y*inv; o[k4*4+2] = v.z*inv; o[k4*4+3] = v.w*inv;
        }
        float mean = 0.f;
        #pragma unroll
        for (int d = 0; d < 16; d++) mean += o[d];
        mean += __shfl_xor_sync(0xffffffffu, mean, 1);
        mean += __shfl_xor_sync(0xffffffffu, mean, 2);
        mean *= (1.f / 64.f);
        float var = 0.f;
        #pragma unroll
        for (int d = 0; d < 16; d++) { float df = o[d] - mean; var += df * df; }
        var += __shfl_xor_sync(0xffffffffu, var, 1);
        var += __shfl_xor_sync(0xffffffffu, var, 2);
        var *= (1.f / 64.f);
        float rstd = rsqrtf(var + 1e-5f);
        size_t obase = ((size_t)(b*Sq + i)) * INNERq + h*DHq + qd*16;
        #pragma unroll
        for (int d = 0; d < 16; d++) {
            int c = h*DHq + qd*16 + d;
            float hn  = (o[d] - mean) * rstd * norm_w[c];
            float za  = g_z[obase + d];
            float sil = za / (1.f + __expf(-za));
            g_h[obase + d] = (hn + skipw[c] * g_xa[obase + d]) * sil;
        }
    }
}

// ---------------- launch ----------------
extern "C" void kernel_launch(void* const* d_in, const int* in_sizes, int n_in,
                              void* d_out, int out_size)
{
    const float* x      = (const float*)d_in[0];
    const float* W_up   = (const float*)d_in[1];
    const float* conv_w = (const float*)d_in[2];
    const float* conv_b = (const float*)d_in[3];
    const float* Wq     = (const float*)d_in[4];
    const float* Wk     = (const float*)d_in[5];
    const float* Wv     = (const float*)d_in[6];
    const float* W_i    = (const float*)d_in[7];
    const float* b_i    = (const float*)d_in[8];
    const float* W_f    = (const float*)d_in[9];
    const float* b_f    = (const float*)d_in[10];
    const float* norm_w = (const float*)d_in[11];
    const float* skipw  = (const float*)d_in[12];
    const float* W_down = (const float*)d_in[13];
    float* out = (float*)d_out;

    cudaFuncSetAttribute(attn_kernel,
                         cudaFuncAttributeMaxDynamicSharedMemorySize, ATT_SMEM_BYTES);

    gemm_nt<0><<<dim3(16, 64), 256>>>(x, W_up, nullptr, Cdim);
    fused_conv_qkv<<<Bq*Sq, 128>>>(conv_w, conv_b, Wq, Wk, Wv);
    gates_kernel<<<32, 256>>>(W_i, b_i, W_f, b_f);
    scan_kernel<<<Bq*NHq, 1024>>>();
    attn_kernel<<<512, 256, ATT_SMEM_BYTES>>>(norm_w, skipw);
    gemm_nt<1><<<dim3(4, 64), 256>>>(nullptr, W_down, out, INNERq);
}

// round 11
// speedup vs baseline: 1.0430x; 1.0430x over previous
#include <cuda_runtime.h>
#include <math.h>

#define Bq    4
#define Sq    1024
#define Cdim  256
#define INNERq 512
#define NHq   8
#define DHq   64

// ---------------- scratch (static __device__, no allocation) ----------------
__device__ float g_xm[Bq*Sq*INNERq];
__device__ float g_z [Bq*Sq*INNERq];
__device__ float g_xa[Bq*Sq*INNERq];
__device__ float g_q [Bq*Sq*INNERq];
__device__ float g_k [Bq*Sq*INNERq];
__device__ float g_v [Bq*Sq*INNERq];
__device__ float g_ig[Bq*NHq*Sq];
__device__ float g_fg[Bq*NHq*Sq];
__device__ float g_lc[Bq*NHq*Sq];
__device__ float g_h [Bq*Sq*INNERq];

// ---------------- NT GEMM: C[m,n] = sum_k A[m,k]*B[n,k], k-tile 32 ----------------
template<int MODE>
__global__ __launch_bounds__(256) void gemm_nt(
    const float* __restrict__ Aext, const float* __restrict__ Bm,
    float* __restrict__ outext, int Kd)
{
    __shared__ float As[32][65];
    __shared__ float Bs[32][65];
    const float* A = (MODE == 0) ? Aext : g_h;
    int tid = threadIdx.x;
    int m0 = blockIdx.y * 64, n0 = blockIdx.x * 64;
    int ty = tid >> 4, tx = tid & 15;
    int lr  = tid >> 2;          // 0..63
    int lc8 = (tid & 3) << 3;    // 0,8,16,24
    float acc[4][4] = {};
    const float* Ap = A  + (size_t)(m0 + lr) * Kd + lc8;
    const float* Bp = Bm + (size_t)(n0 + lr) * Kd + lc8;
    for (int k0 = 0; k0 < Kd; k0 += 32) {
        float4 a0 = *(const float4*)(Ap + k0);
        float4 a1 = *(const float4*)(Ap + k0 + 4);
        float4 b0 = *(const float4*)(Bp + k0);
        float4 b1 = *(const float4*)(Bp + k0 + 4);
        As[lc8+0][lr] = a0.x; As[lc8+1][lr] = a0.y; As[lc8+2][lr] = a0.z; As[lc8+3][lr] = a0.w;
        As[lc8+4][lr] = a1.x; As[lc8+5][lr] = a1.y; As[lc8+6][lr] = a1.z; As[lc8+7][lr] = a1.w;
        Bs[lc8+0][lr] = b0.x; Bs[lc8+1][lr] = b0.y; Bs[lc8+2][lr] = b0.z; Bs[lc8+3][lr] = b0.w;
        Bs[lc8+4][lr] = b1.x; Bs[lc8+5][lr] = b1.y; Bs[lc8+6][lr] = b1.z; Bs[lc8+7][lr] = b1.w;
        __syncthreads();
        #pragma unroll
        for (int kk = 0; kk < 32; kk++) {
            float a[4], b[4];
            #pragma unroll
            for (int i = 0; i < 4; i++) { a[i] = As[kk][ty*4+i]; b[i] = Bs[kk][tx*4+i]; }
            #pragma unroll
            for (int i = 0; i < 4; i++)
                #pragma unroll
                for (int j = 0; j < 4; j++) acc[i][j] += a[i] * b[j];
        }
        __syncthreads();
    }
    #pragma unroll
    for (int i = 0; i < 4; i++) {
        int m = m0 + ty*4 + i;
        #pragma unroll
        for (int j = 0; j < 4; j++) {
            int n = n0 + tx*4 + j;
            if (MODE == 0) {
                if (n < INNERq) g_xm[(size_t)m * INNERq + n] = acc[i][j];
                else            g_z [(size_t)m * INNERq + (n - INNERq)] = acc[i][j];
            } else {
                outext[(size_t)m * Cdim + n] = acc[i][j];
            }
        }
    }
}

// ---------------- conv + silu + per-block qkv (gates moved out) ----------------
__global__ __launch_bounds__(128) void fused_conv_qkv(
    const float* __restrict__ conv_w, const float* __restrict__ conv_b,
    const float* __restrict__ Wq, const float* __restrict__ Wk, const float* __restrict__ Wv)
{
    int bs = blockIdx.x;
    int b = bs >> 10;
    int s = bs & 1023;
    int t = threadIdx.x;
    size_t rowbase = (size_t)bs * INNERq;

    float xm4[4], xa4[4];
    #pragma unroll
    for (int j = 0; j < 4; j++) {
        int c = t*4 + j;
        float a = conv_b[c];
        #pragma unroll
        for (int kk = 0; kk < 4; kk++) {
            int sp = s - 3 + kk;
            if (sp >= 0) a += g_xm[((size_t)(b*Sq + sp)) * INNERq + c] * conv_w[c*4 + kk];
        }
        float sg = 1.f / (1.f + __expf(-a));
        xa4[j] = a * sg;
        g_xa[rowbase + c] = xa4[j];
        xm4[j] = g_xm[rowbase + c];
    }

    float q4[4], k4[4], v4[4];
    #pragma unroll
    for (int o = 0; o < 4; o++) {
        float aq = 0.f, ak = 0.f, av = 0.f;
        #pragma unroll
        for (int d = 0; d < 4; d++) {
            aq += Wq[t*16 + o*4 + d] * xa4[d];
            ak += Wk[t*16 + o*4 + d] * xa4[d];
            av += Wv[t*16 + o*4 + d] * xm4[d];
        }
        q4[o] = aq; k4[o] = ak; v4[o] = av;
    }
    *(float4*)&g_q[rowbase + t*4] = make_float4(q4[0], q4[1], q4[2], q4[3]);
    *(float4*)&g_k[rowbase + t*4] = make_float4(k4[0], k4[1], k4[2], k4[3]);
    *(float4*)&g_v[rowbase + t*4] = make_float4(v4[0], v4[1], v4[2], v4[3]);
}

// ---------------- gates as GEMM: [4096,16] = [q|k|v](4096x1536) @ W^T ----------------
__global__ __launch_bounds__(256) void gates_kernel(
    const float* __restrict__ W_i, const float* __restrict__ b_i,
    const float* __restrict__ W_f, const float* __restrict__ b_f)
{
    __shared__ float Wt[16][132];      // row stride 528B = 33*16 (16B aligned)
    __shared__ float red[128][17];
    int t = threadIdx.x;
    int r = t & 127;
    int half = t >> 7;
    int row = blockIdx.x * 128 + r;
    int b = row >> 10, s = row & 1023;

    float acc[16];
    #pragma unroll
    for (int g = 0; g < 16; g++) acc[g] = 0.f;

    #pragma unroll
    for (int seg = 0; seg < 3; seg++) {
        const float* src = (seg == 0) ? g_q : (seg == 1) ? g_k : g_v;
        const float* base = src + (size_t)row * INNERq;
        for (int k0 = 0; k0 < 512; k0 += 128) {
            #pragma unroll
            for (int i = 0; i < 2; i++) {
                int e = t + 256*i;
                int g = e >> 5;
                int c4 = (e & 31) << 2;
                const float* Wsrc = (g < 8) ? (W_i + g*1536) : (W_f + (g-8)*1536);
                *(float4*)&Wt[g][c4] = *(const float4*)&Wsrc[seg*512 + k0 + c4];
            }
            __syncthreads();
            int kbeg = half * 64;
            #pragma unroll 4
            for (int k4 = kbeg; k4 < kbeg + 64; k4 += 4) {
                float4 a = *(const float4*)&base[k0 + k4];
                #pragma unroll
                for (int g = 0; g < 16; g++) {
                    float4 w = *(const float4*)&Wt[g][k4];
                    acc[g] += a.x*w.x + a.y*w.y + a.z*w.z + a.w*w.w;
                }
            }
            __syncthreads();
        }
    }
    if (half == 1) {
        #pragma unroll
        for (int g = 0; g < 16; g++) red[r][g] = acc[g];
    }
    __syncthreads();
    if (half == 0) {
        #pragma unroll
        for (int h = 0; h < 8; h++) {
            float ig = acc[h]   + red[r][h]   + b_i[h];
            float fg = acc[8+h] + red[r][8+h] + b_f[h];
            g_ig[(size_t)(b*NHq + h) * Sq + s] = ig;
            g_fg[(size_t)(b*NHq + h) * Sq + s] = fg;
        }
    }
}

// ---------------- log-sigmoid + inclusive cumsum over S per (b,h) ----------------
__global__ __launch_bounds__(1024) void scan_kernel()
{
    int bh = blockIdx.x;
    int s = threadIdx.x;
    float x = g_fg[(size_t)bh * Sq + s];
    float lf = fminf(x, 0.f) - log1pf(expf(-fabsf(x)));
    __shared__ float sc[Sq];
    sc[s] = lf;
    __syncthreads();
    for (int off = 1; off < Sq; off <<= 1) {
        float tv = (s >= off) ? sc[s - off] : 0.f;
        __syncthreads();
        sc[s] += tv;
        __syncthreads();
    }
    g_lc[(size_t)bh * Sq + s] = sc[s];
}

// ---------------- streaming mLSTM attention v4c: 64x64 tiles, natural regs (no forced 4/SM) ----------------
#define ATT_STRIDE 68
#define ATT_SMEM_FLOATS (3*64*ATT_STRIDE + 7*64)
#define ATT_SMEM_BYTES  (ATT_SMEM_FLOATS*4)

__global__ __launch_bounds__(256) void attn_kernel(
    const float* __restrict__ norm_w, const float* __restrict__ skipw)
{
    extern __shared__ float sm[];
    float* Qt = sm;                       // [64][68] Q^T (reused as O)
    float* KV = Qt + 64*ATT_STRIDE;       // [64][68] K^T then V
    float* Pt = KV + 64*ATT_STRIDE;       // [64][68] P row-major
    float* pm       = Pt + 64*ATT_STRIDE;
    float* ej       = pm + 64;
    float* m_row    = ej + 64;
    float* sc_row   = m_row + 64;
    float* Ei_row   = sc_row + 64;
    float* ssum_row = Ei_row + 64;
    float* lci_row  = ssum_row + 64;

    int xblk = blockIdx.x;
    int it = 15 - (xblk >> 5);
    int bh = xblk & 31;
    int b = bh >> 3, h = bh & 7;
    int i0 = it * 64;
    int t = threadIdx.x;
    int tx = t & 15, ty = t >> 4;

    #pragma unroll
    for (int e4 = 0; e4 < 4; e4++) {
        int e = t + 256 * e4;
        int row = e >> 4, c4 = (e & 15) << 2;
        float4 qv = *(const float4*)&g_q[((size_t)(b*Sq + i0 + row)) * INNERq + h*DHq + c4];
        Qt[(c4+0)*ATT_STRIDE + row] = qv.x;
        Qt[(c4+1)*ATT_STRIDE + row] = qv.y;
        Qt[(c4+2)*ATT_STRIDE + row] = qv.z;
        Qt[(c4+3)*ATT_STRIDE + row] = qv.w;
    }
    if (t < 64) {
        lci_row[t]  = g_lc[(size_t)bh*Sq + i0 + t];
        m_row[t]    = -3.4e38f;
        ssum_row[t] = 0.f;
    }

    float acc[4][4];
    #pragma unroll
    for (int a = 0; a < 4; a++)
        #pragma unroll
        for (int d = 0; d < 4; d++) acc[a][d] = 0.f;

    for (int jt = 0; jt <= it; jt++) {
        int j0 = jt * 64;
        __syncthreads();

        #pragma unroll
        for (int e4 = 0; e4 < 4; e4++) {
            int e = t + 256*e4;
            int row = e >> 4, c4 = (e & 15) << 2;
            float4 kv = *(const float4*)&g_k[((size_t)(b*Sq + j0 + row)) * INNERq + h*DHq + c4];
            KV[(c4+0)*ATT_STRIDE + row] = kv.x*0.125f;
            KV[(c4+1)*ATT_STRIDE + row] = kv.y*0.125f;
            KV[(c4+2)*ATT_STRIDE + row] = kv.z*0.125f;
            KV[(c4+3)*ATT_STRIDE + row] = kv.w*0.125f;
        }
        if (t < 32) {
            int l = t;
            size_t gbase = (size_t)bh*Sq + j0;
            float a0 = g_ig[gbase + l]      - g_lc[gbase + l];
            float a1 = g_ig[gbase + 32 + l] - g_lc[gbase + 32 + l];
            float p0 = a0;
            #pragma unroll
            for (int off = 1; off < 32; off <<= 1) {
                float u = __shfl_up_sync(0xffffffffu, p0, off);
                if (l >= off) p0 = fmaxf(p0, u);
            }
            float max0 = __shfl_sync(0xffffffffu, p0, 31);
            float p1 = a1;
            #pragma unroll
            for (int off = 1; off < 32; off <<= 1) {
                float u = __shfl_up_sync(0xffffffffu, p1, off);
                if (l >= off) p1 = fmaxf(p1, u);
            }
            p1 = fmaxf(p1, max0);
            float pmAll = __shfl_sync(0xffffffffu, p1, 31);
            pm[l]      = p0;
            pm[32 + l] = p1;
            ej[l]      = __expf(a0 - pmAll);
            ej[32 + l] = __expf(a1 - pmAll);
            __syncwarp();
            #pragma unroll
            for (int half = 0; half < 2; half++) {
                int r = l + 32*half;
                int jm = i0 + r - j0 + 1;
                jm = jm > 64 ? 64 : jm;
                float mo = m_row[r];
                float rowmax = lci_row[r] + pm[jm-1];
                float mnew = fmaxf(mo, rowmax);
                float sc = __expf(mo - mnew);
                sc_row[r] = sc;
                Ei_row[r] = __expf(lci_row[r] + pmAll - mnew);
                m_row[r]  = mnew;
                ssum_row[r] *= sc;
            }
        }
        __syncthreads();

        #pragma unroll
        for (int a = 0; a < 4; a++) {
            float sc = sc_row[4*ty + a];
            #pragma unroll
            for (int d = 0; d < 4; d++) acc[a][d] *= sc;
        }

        float s[4][4];
        #pragma unroll
        for (int a = 0; a < 4; a++)
            #pragma unroll
            for (int c = 0; c < 4; c++) s[a][c] = 0.f;
        #pragma unroll 8
        for (int kk = 0; kk < 64; kk++) {
            float4 aq = *(const float4*)&Qt[kk*ATT_STRIDE + 4*ty];
            float4 bk = *(const float4*)&KV[kk*ATT_STRIDE + 4*tx];
            s[0][0] += aq.x*bk.x; s[0][1] += aq.x*bk.y; s[0][2] += aq.x*bk.z; s[0][3] += aq.x*bk.w;
            s[1][0] += aq.y*bk.x; s[1][1] += aq.y*bk.y; s[1][2] += aq.y*bk.z; s[1][3] += aq.y*bk.w;
            s[2][0] += aq.z*bk.x; s[2][1] += aq.z*bk.y; s[2][2] += aq.z*bk.z; s[2][3] += aq.z*bk.w;
            s[3][0] += aq.w*bk.x; s[3][1] += aq.w*bk.y; s[3][2] += aq.w*bk.z; s[3][3] += aq.w*bk.w;
        }
        {
            float e0 = ej[4*tx], e1 = ej[4*tx+1], e2 = ej[4*tx+2], e3 = ej[4*tx+3];
            bool diag = (jt == it);
            int jg = j0 + 4*tx;
            #pragma unroll
            for (int a = 0; a < 4; a++) {
                int rr = 4*ty + a;
                float Ei = Ei_row[rr];
                float p0 = s[a][0]*Ei*e0;
                float p1 = s[a][1]*Ei*e1;
                float p2 = s[a][2]*Ei*e2;
                float p3 = s[a][3]*Ei*e3;
                if (diag) {
                    int ig = i0 + rr;
                    if (jg     > ig) p0 = 0.f;
                    if (jg + 1 > ig) p1 = 0.f;
                    if (jg + 2 > ig) p2 = 0.f;
                    if (jg + 3 > ig) p3 = 0.f;
                }
                *(float4*)&Pt[rr*ATT_STRIDE + 4*tx] = make_float4(p0, p1, p2, p3);
                float part = (p0 + p1) + (p2 + p3);
                part += __shfl_xor_sync(0xffffffffu, part, 1);
                part += __shfl_xor_sync(0xffffffffu, part, 2);
                part += __shfl_xor_sync(0xffffffffu, part, 4);
                part += __shfl_xor_sync(0xffffffffu, part, 8);
                if (tx == 0) ssum_row[rr] += part;
            }
        }
        __syncthreads();

        #pragma unroll
        for (int e4 = 0; e4 < 4; e4++) {
            int e = t + 256*e4;
            int row = e >> 4, c4 = (e & 15) << 2;
            *(float4*)&KV[row*ATT_STRIDE + c4] =
                *(const float4*)&g_v[((size_t)(b*Sq + j0 + row)) * INNERq + h*DHq + c4];
        }
        __syncthreads();

        #pragma unroll 4
        for (int jj = 0; jj < 64; jj += 4) {
            float4 pa0 = *(const float4*)&Pt[(4*ty+0)*ATT_STRIDE + jj];
            float4 pa1 = *(const float4*)&Pt[(4*ty+1)*ATT_STRIDE + jj];
            float4 pa2 = *(const float4*)&Pt[(4*ty+2)*ATT_STRIDE + jj];
            float4 pa3 = *(const float4*)&Pt[(4*ty+3)*ATT_STRIDE + jj];
            float4 vb0 = *(const float4*)&KV[(jj+0)*ATT_STRIDE + 4*tx];
            float4 vb1 = *(const float4*)&KV[(jj+1)*ATT_STRIDE + 4*tx];
            float4 vb2 = *(const float4*)&KV[(jj+2)*ATT_STRIDE + 4*tx];
            float4 vb3 = *(const float4*)&KV[(jj+3)*ATT_STRIDE + 4*tx];
            acc[0][0] += pa0.x*vb0.x + pa0.y*vb1.x + pa0.z*vb2.x + pa0.w*vb3.x;
            acc[0][1] += pa0.x*vb0.y + pa0.y*vb1.y + pa0.z*vb2.y + pa0.w*vb3.y;
            acc[0][2] += pa0.x*vb0.z + pa0.y*vb1.z + pa0.z*vb2.z + pa0.w*vb3.z;
            acc[0][3] += pa0.x*vb0.w + pa0.y*vb1.w + pa0.z*vb2.w + pa0.w*vb3.w;
            acc[1][0] += pa1.x*vb0.x + pa1.y*vb1.x + pa1.z*vb2.x + pa1.w*vb3.x;
            acc[1][1] += pa1.x*vb0.y + pa1.y*vb1.y + pa1.z*vb2.y + pa1.w*vb3.y;
            acc[1][2] += pa1.x*vb0.z + pa1.y*vb1.z + pa1.z*vb2.z + pa1.w*vb3.z;
            acc[1][3] += pa1.x*vb0.w + pa1.y*vb1.w + pa1.z*vb2.w + pa1.w*vb3.w;
            acc[2][0] += pa2.x*vb0.x + pa2.y*vb1.x + pa2.z*vb2.x + pa2.w*vb3.x;
            acc[2][1] += pa2.x*vb0.y + pa2.y*vb1.y + pa2.z*vb2.y + pa2.w*vb3.y;
            acc[2][2] += pa2.x*vb0.z + pa2.y*vb1.z + pa2.z*vb2.z + pa2.w*vb3.z;
            acc[2][3] += pa2.x*vb0.w + pa2.y*vb1.w + pa2.z*vb2.w + pa2.w*vb3.w;
            acc[3][0] += pa3.x*vb0.x + pa3.y*vb1.x + pa3.z*vb2.x + pa3.w*vb3.x;
            acc[3][1] += pa3.x*vb0.y + pa3.y*vb1.y + pa3.z*vb2.y + pa3.w*vb3.y;
            acc[3][2] += pa3.x*vb0.z + pa3.y*vb1.z + pa3.z*vb2.z + pa3.w*vb3.z;
            acc[3][3] += pa3.x*vb0.w + pa3.y*vb1.w + pa3.z*vb2.w + pa3.w*vb3.w;
        }
    }

    #pragma unroll
    for (int a = 0; a < 4; a++)
        *(float4*)&Qt[(4*ty + a)*ATT_STRIDE + 4*tx] =
            make_float4(acc[a][0], acc[a][1], acc[a][2], acc[a][3]);
    __syncthreads();

    {
        int row = t >> 2, qd = t & 3;
        int i = i0 + row;
        float m    = m_row[row];
        float ssum = ssum_row[row];
        float denom = fmaxf(fabsf(ssum), __expf(-m)) + 1e-6f;
        float inv = 1.f / denom;
        float o[16];
        #pragma unroll
        for (int k4 = 0; k4 < 4; k4++) {
            float4 v = *(const float4*)&Qt[row*ATT_STRIDE + qd*16 + k4*4];
            o[k4*4+0] = v.x*inv; o[k4*4+1] = v.y*inv; o[k4*4+2] = v.z*inv; o[k4*4+3] = v.w*inv;
        }
        float mean = 0.f;
        #pragma unroll
        for (int d = 0; d < 16; d++) mean += o[d];
        mean += __shfl_xor_sync(0xffffffffu, mean, 1);
        mean += __shfl_xor_sync(0xffffffffu, mean, 2);
        mean *= (1.f / 64.f);
        float var = 0.f;
        #pragma unroll
        for (int d = 0; d < 16; d++) { float df = o[d] - mean; var += df * df; }
        var += __shfl_xor_sync(0xffffffffu, var, 1);
        var += __shfl_xor_sync(0xffffffffu, var, 2);
        var *= (1.f / 64.f);
        float rstd = rsqrtf(var + 1e-5f);
        size_t obase = ((size_t)(b*Sq + i)) * INNERq + h*DHq + qd*16;
        #pragma unroll
        for (int d = 0; d < 16; d++) {
            int c = h*DHq + qd*16 + d;
            float hn  = (o[d] - mean) * rstd * norm_w[c];
            float za  = g_z[obase + d];
            float sil = za / (1.f + __expf(-za));
            g_h[obase + d] = (hn + skipw[c] * g_xa[obase + d]) * sil;
        }
    }
}

// ---------------- launch ----------------
extern "C" void kernel_launch(void* const* d_in, const int* in_sizes, int n_in,
                              void* d_out, int out_size)
{
    const float* x      = (const float*)d_in[0];
    const float* W_up   = (const float*)d_in[1];
    const float* conv_w = (const float*)d_in[2];
    const float* conv_b = (const float*)d_in[3];
    const float* Wq     = (const float*)d_in[4];
    const float* Wk     = (const float*)d_in[5];
    const float* Wv     = (const float*)d_in[6];
    const float* W_i    = (const float*)d_in[7];
    const float* b_i    = (const float*)d_in[8];
    const float* W_f    = (const float*)d_in[9];
    const float* b_f    = (const float*)d_in[10];
    const float* norm_w = (const float*)d_in[11];
    const float* skipw  = (const float*)d_in[12];
    const float* W_down = (const float*)d_in[13];
    float* out = (float*)d_out;

    cudaFuncSetAttribute(attn_kernel,
                         cudaFuncAttributeMaxDynamicSharedMemorySize, ATT_SMEM_BYTES);

    gemm_nt<0><<<dim3(16, 64), 256>>>(x, W_up, nullptr, Cdim);
    fused_conv_qkv<<<Bq*Sq, 128>>>(conv_w, conv_b, Wq, Wk, Wv);
    gates_kernel<<<32, 256>>>(W_i, b_i, W_f, b_f);
    scan_kernel<<<Bq*NHq, 1024>>>();
    attn_kernel<<<512, 256, ATT_SMEM_BYTES>>>(norm_w, skipw);
    gemm_nt<1><<<dim3(4, 64), 256>>>(nullptr, W_down, out, INNERq);
}

// round 12
// speedup vs baseline: 1.1204x; 1.0742x over previous
#include <cuda_runtime.h>
#include <math.h>

#define Bq    4
#define Sq    1024
#define Cdim  256
#define INNERq 512
#define NHq   8
#define DHq   64

// ---------------- scratch (static __device__, no allocation) ----------------
__device__ float g_xm[Bq*Sq*INNERq];
__device__ float g_z [Bq*Sq*INNERq];
__device__ float g_xa[Bq*Sq*INNERq];
__device__ float g_q [Bq*Sq*INNERq];
__device__ float g_k [Bq*Sq*INNERq];
__device__ float g_v [Bq*Sq*INNERq];
__device__ float g_ig[Bq*NHq*Sq];
__device__ float g_fg[Bq*NHq*Sq];
__device__ float g_lc[Bq*NHq*Sq];
__device__ float g_h [Bq*Sq*INNERq];

// ---------------- NT GEMM: C[m,n] = sum_k A[m,k]*B[n,k] (k-tile 16, R7 version) ----------------
template<int MODE>
__global__ __launch_bounds__(256) void gemm_nt(
    const float* __restrict__ Aext, const float* __restrict__ Bm,
    float* __restrict__ outext, int Kd)
{
    __shared__ float As[16][65];
    __shared__ float Bs[16][65];
    const float* A = (MODE == 0) ? Aext : g_h;
    int tid = threadIdx.x;
    int m0 = blockIdx.y * 64, n0 = blockIdx.x * 64;
    int ty = tid >> 4, tx = tid & 15;
    int lr  = tid >> 2;
    int lc4 = (tid & 3) << 2;
    float acc[4][4] = {};
    const float* Ap = A  + (size_t)(m0 + lr) * Kd + lc4;
    const float* Bp = Bm + (size_t)(n0 + lr) * Kd + lc4;
    for (int k0 = 0; k0 < Kd; k0 += 16) {
        float4 av = *(const float4*)(Ap + k0);
        float4 bv = *(const float4*)(Bp + k0);
        As[lc4+0][lr] = av.x; As[lc4+1][lr] = av.y; As[lc4+2][lr] = av.z; As[lc4+3][lr] = av.w;
        Bs[lc4+0][lr] = bv.x; Bs[lc4+1][lr] = bv.y; Bs[lc4+2][lr] = bv.z; Bs[lc4+3][lr] = bv.w;
        __syncthreads();
        #pragma unroll
        for (int kk = 0; kk < 16; kk++) {
            float a[4], b[4];
            #pragma unroll
            for (int i = 0; i < 4; i++) { a[i] = As[kk][ty*4+i]; b[i] = Bs[kk][tx*4+i]; }
            #pragma unroll
            for (int i = 0; i < 4; i++)
                #pragma unroll
                for (int j = 0; j < 4; j++) acc[i][j] += a[i] * b[j];
        }
        __syncthreads();
    }
    #pragma unroll
    for (int i = 0; i < 4; i++) {
        int m = m0 + ty*4 + i;
        #pragma unroll
        for (int j = 0; j < 4; j++) {
            int n = n0 + tx*4 + j;
            if (MODE == 0) {
                if (n < INNERq) g_xm[(size_t)m * INNERq + n] = acc[i][j];
                else            g_z [(size_t)m * INNERq + (n - INNERq)] = acc[i][j];
            } else {
                outext[(size_t)m * Cdim + n] = acc[i][j];
            }
        }
    }
}

// ---------------- conv + silu + per-block qkv (gates split out) ----------------
__global__ __launch_bounds__(128) void fused_conv_qkv(
    const float* __restrict__ conv_w, const float* __restrict__ conv_b,
    const float* __restrict__ Wq, const float* __restrict__ Wk, const float* __restrict__ Wv)
{
    int bs = blockIdx.x;
    int b = bs >> 10;
    int s = bs & 1023;
    int t = threadIdx.x;
    size_t rowbase = (size_t)bs * INNERq;

    float xm4[4], xa4[4];
    #pragma unroll
    for (int j = 0; j < 4; j++) {
        int c = t*4 + j;
        float a = conv_b[c];
        #pragma unroll
        for (int kk = 0; kk < 4; kk++) {
            int sp = s - 3 + kk;
            if (sp >= 0) a += g_xm[((size_t)(b*Sq + sp)) * INNERq + c] * conv_w[c*4 + kk];
        }
        float sg = 1.f / (1.f + __expf(-a));
        xa4[j] = a * sg;
        g_xa[rowbase + c] = xa4[j];
        xm4[j] = g_xm[rowbase + c];
    }

    float q4[4], k4[4], v4[4];
    #pragma unroll
    for (int o = 0; o < 4; o++) {
        float aq = 0.f, ak = 0.f, av = 0.f;
        #pragma unroll
        for (int d = 0; d < 4; d++) {
            aq += Wq[t*16 + o*4 + d] * xa4[d];
            ak += Wk[t*16 + o*4 + d] * xa4[d];
            av += Wv[t*16 + o*4 + d] * xm4[d];
        }
        q4[o] = aq; k4[o] = ak; v4[o] = av;
    }
    *(float4*)&g_q[rowbase + t*4] = make_float4(q4[0], q4[1], q4[2], q4[3]);
    *(float4*)&g_k[rowbase + t*4] = make_float4(k4[0], k4[1], k4[2], k4[3]);
    *(float4*)&g_v[rowbase + t*4] = make_float4(v4[0], v4[1], v4[2], v4[3]);
}

// ---------------- gates v2: 256 blocks x 16 rows; thread = (row r=t>>4, kslice ks=t&15) ----------------
// Coalesced A reads (ks spans 128 contiguous floats per row), W tiles in smem,
// two-stage smem reduction over kslices.
__global__ __launch_bounds__(256) void gates_kernel(
    const float* __restrict__ W_i, const float* __restrict__ b_i,
    const float* __restrict__ W_f, const float* __restrict__ b_f)
{
    __shared__ float Wt[16][132];        // 16 gates x 128 k (rows 528B = 16B-aligned)
    __shared__ float red[16][16][17];    // [ks][r][g]
    int t = threadIdx.x;
    int r  = t >> 4;      // row within block 0..15
    int ks = t & 15;      // k-slice 0..15 (8 floats each within a 128-k tile)
    int row = blockIdx.x * 16 + r;

    float acc[16];
    #pragma unroll
    for (int g = 0; g < 16; g++) acc[g] = 0.f;

    #pragma unroll
    for (int tt = 0; tt < 12; tt++) {
        int seg = tt >> 2;              // 0:q 1:k 2:v
        int k0  = (tt & 3) * 128;
        const float* src = (seg == 0) ? g_q : (seg == 1) ? g_k : g_v;
        // cooperative W tile load: 512 float4 over 256 threads
        #pragma unroll
        for (int i = 0; i < 2; i++) {
            int e = t + 256*i;
            int g = e >> 5;
            int c4 = (e & 31) << 2;
            const float* Wsrc = (g < 8) ? (W_i + g*1536) : (W_f + (g-8)*1536);
            *(float4*)&Wt[g][c4] = *(const float4*)&Wsrc[seg*512 + k0 + c4];
        }
        __syncthreads();
        const float* base = src + (size_t)row * INNERq + k0 + ks*8;
        float4 a0 = *(const float4*)(base);
        float4 a1 = *(const float4*)(base + 4);
        #pragma unroll
        for (int g = 0; g < 16; g++) {
            float4 w0 = *(const float4*)&Wt[g][ks*8];
            float4 w1 = *(const float4*)&Wt[g][ks*8 + 4];
            acc[g] += a0.x*w0.x + a0.y*w0.y + a0.z*w0.z + a0.w*w0.w
                    + a1.x*w1.x + a1.y*w1.y + a1.z*w1.z + a1.w*w1.w;
        }
        __syncthreads();
    }
    // stage partials
    #pragma unroll
    for (int g = 0; g < 16; g++) red[ks][r][g] = acc[g];
    __syncthreads();
    // reduce: thread (r2 = t>>4, g2 = t&15) sums over 16 kslices
    {
        int r2 = t >> 4, g2 = t & 15;
        float sum = 0.f;
        #pragma unroll
        for (int k2 = 0; k2 < 16; k2++) sum += red[k2][r2][g2];
        int row2 = blockIdx.x * 16 + r2;
        int b2 = row2 >> 10, s2 = row2 & 1023;
        int h = g2 & 7;
        if (g2 < 8) g_ig[(size_t)(b2*NHq + h) * Sq + s2] = sum + b_i[h];
        else        g_fg[(size_t)(b2*NHq + h) * Sq + s2] = sum + b_f[h];
    }
}

// ---------------- log-sigmoid + inclusive cumsum over S per (b,h) ----------------
__global__ __launch_bounds__(1024) void scan_kernel()
{
    int bh = blockIdx.x;
    int s = threadIdx.x;
    float x = g_fg[(size_t)bh * Sq + s];
    float lf = fminf(x, 0.f) - log1pf(expf(-fabsf(x)));
    __shared__ float sc[Sq];
    sc[s] = lf;
    __syncthreads();
    for (int off = 1; off < Sq; off <<= 1) {
        float tv = (s >= off) ? sc[s - off] : 0.f;
        __syncthreads();
        sc[s] += tv;
        __syncthreads();
    }
    g_lc[(size_t)bh * Sq + s] = sc[s];
}

// ---------------- streaming mLSTM attention (R7 version: 64x64 tiles, 4x4 micro, natural regs) ----------------
#define ATT_STRIDE 68
#define ATT_SMEM_FLOATS (3*64*ATT_STRIDE + 7*64)
#define ATT_SMEM_BYTES  (ATT_SMEM_FLOATS*4)

__global__ __launch_bounds__(256) void attn_kernel(
    const float* __restrict__ norm_w, const float* __restrict__ skipw)
{
    extern __shared__ float sm[];
    float* Qt = sm;
    float* KV = Qt + 64*ATT_STRIDE;
    float* Pt = KV + 64*ATT_STRIDE;
    float* pm       = Pt + 64*ATT_STRIDE;
    float* ej       = pm + 64;
    float* m_row    = ej + 64;
    float* sc_row   = m_row + 64;
    float* Ei_row   = sc_row + 64;
    float* ssum_row = Ei_row + 64;
    float* lci_row  = ssum_row + 64;

    int xblk = blockIdx.x;
    int it = 15 - (xblk >> 5);
    int bh = xblk & 31;
    int b = bh >> 3, h = bh & 7;
    int i0 = it * 64;
    int t = threadIdx.x;
    int tx = t & 15, ty = t >> 4;

    #pragma unroll
    for (int e4 = 0; e4 < 4; e4++) {
        int e = t + 256 * e4;
        int row = e >> 4, c4 = (e & 15) << 2;
        float4 qv = *(const float4*)&g_q[((size_t)(b*Sq + i0 + row)) * INNERq + h*DHq + c4];
        Qt[(c4+0)*ATT_STRIDE + row] = qv.x;
        Qt[(c4+1)*ATT_STRIDE + row] = qv.y;
        Qt[(c4+2)*ATT_STRIDE + row] = qv.z;
        Qt[(c4+3)*ATT_STRIDE + row] = qv.w;
    }
    if (t < 64) {
        lci_row[t]  = g_lc[(size_t)bh*Sq + i0 + t];
        m_row[t]    = -3.4e38f;
        ssum_row[t] = 0.f;
    }

    float acc[4][4];
    #pragma unroll
    for (int a = 0; a < 4; a++)
        #pragma unroll
        for (int d = 0; d < 4; d++) acc[a][d] = 0.f;

    for (int jt = 0; jt <= it; jt++) {
        int j0 = jt * 64;
        __syncthreads();

        #pragma unroll
        for (int e4 = 0; e4 < 4; e4++) {
            int e = t + 256*e4;
            int row = e >> 4, c4 = (e & 15) << 2;
            float4 kv = *(const float4*)&g_k[((size_t)(b*Sq + j0 + row)) * INNERq + h*DHq + c4];
            KV[(c4+0)*ATT_STRIDE + row] = kv.x*0.125f;
            KV[(c4+1)*ATT_STRIDE + row] = kv.y*0.125f;
            KV[(c4+2)*ATT_STRIDE + row] = kv.z*0.125f;
            KV[(c4+3)*ATT_STRIDE + row] = kv.w*0.125f;
        }
        if (t < 32) {
            int l = t;
            size_t gbase = (size_t)bh*Sq + j0;
            float a0 = g_ig[gbase + l]      - g_lc[gbase + l];
            float a1 = g_ig[gbase + 32 + l] - g_lc[gbase + 32 + l];
            float p0 = a0;
            #pragma unroll
            for (int off = 1; off < 32; off <<= 1) {
                float u = __shfl_up_sync(0xffffffffu, p0, off);
                if (l >= off) p0 = fmaxf(p0, u);
            }
            float max0 = __shfl_sync(0xffffffffu, p0, 31);
            float p1 = a1;
            #pragma unroll
            for (int off = 1; off < 32; off <<= 1) {
                float u = __shfl_up_sync(0xffffffffu, p1, off);
                if (l >= off) p1 = fmaxf(p1, u);
            }
            p1 = fmaxf(p1, max0);
            float pmAll = __shfl_sync(0xffffffffu, p1, 31);
            pm[l]      = p0;
            pm[32 + l] = p1;
            ej[l]      = __expf(a0 - pmAll);
            ej[32 + l] = __expf(a1 - pmAll);
            __syncwarp();
            #pragma unroll
            for (int half = 0; half < 2; half++) {
                int r = l + 32*half;
                int jm = i0 + r - j0 + 1;
                jm = jm > 64 ? 64 : jm;
                float mo = m_row[r];
                float rowmax = lci_row[r] + pm[jm-1];
                float mnew = fmaxf(mo, rowmax);
                float sc = __expf(mo - mnew);
                sc_row[r] = sc;
                Ei_row[r] = __expf(lci_row[r] + pmAll - mnew);
                m_row[r]  = mnew;
                ssum_row[r] *= sc;
            }
        }
        __syncthreads();

        #pragma unroll
        for (int a = 0; a < 4; a++) {
            float sc = sc_row[4*ty + a];
            #pragma unroll
            for (int d = 0; d < 4; d++) acc[a][d] *= sc;
        }

        float s[4][4];
        #pragma unroll
        for (int a = 0; a < 4; a++)
            #pragma unroll
            for (int c = 0; c < 4; c++) s[a][c] = 0.f;
        #pragma unroll 8
        for (int kk = 0; kk < 64; kk++) {
            float4 aq = *(const float4*)&Qt[kk*ATT_STRIDE + 4*ty];
            float4 bk = *(const float4*)&KV[kk*ATT_STRIDE + 4*tx];
            s[0][0] += aq.x*bk.x; s[0][1] += aq.x*bk.y; s[0][2] += aq.x*bk.z; s[0][3] += aq.x*bk.w;
            s[1][0] += aq.y*bk.x; s[1][1] += aq.y*bk.y; s[1][2] += aq.y*bk.z; s[1][3] += aq.y*bk.w;
            s[2][0] += aq.z*bk.x; s[2][1] += aq.z*bk.y; s[2][2] += aq.z*bk.z; s[2][3] += aq.z*bk.w;
            s[3][0] += aq.w*bk.x; s[3][1] += aq.w*bk.y; s[3][2] += aq.w*bk.z; s[3][3] += aq.w*bk.w;
        }
        {
            float e0 = ej[4*tx], e1 = ej[4*tx+1], e2 = ej[4*tx+2], e3 = ej[4*tx+3];
            bool diag = (jt == it);
            int jg = j0 + 4*tx;
            #pragma unroll
            for (int a = 0; a < 4; a++) {
                int rr = 4*ty + a;
                float Ei = Ei_row[rr];
                float p0 = s[a][0]*Ei*e0;
                float p1 = s[a][1]*Ei*e1;
                float p2 = s[a][2]*Ei*e2;
                float p3 = s[a][3]*Ei*e3;
                if (diag) {
                    int ig = i0 + rr;
                    if (jg     > ig) p0 = 0.f;
                    if (jg + 1 > ig) p1 = 0.f;
                    if (jg + 2 > ig) p2 = 0.f;
                    if (jg + 3 > ig) p3 = 0.f;
                }
                *(float4*)&Pt[rr*ATT_STRIDE + 4*tx] = make_float4(p0, p1, p2, p3);
                float part = (p0 + p1) + (p2 + p3);
                part += __shfl_xor_sync(0xffffffffu, part, 1);
                part += __shfl_xor_sync(0xffffffffu, part, 2);
                part += __shfl_xor_sync(0xffffffffu, part, 4);
                part += __shfl_xor_sync(0xffffffffu, part, 8);
                if (tx == 0) ssum_row[rr] += part;
            }
        }
        __syncthreads();

        #pragma unroll
        for (int e4 = 0; e4 < 4; e4++) {
            int e = t + 256*e4;
            int row = e >> 4, c4 = (e & 15) << 2;
            *(float4*)&KV[row*ATT_STRIDE + c4] =
                *(const float4*)&g_v[((size_t)(b*Sq + j0 + row)) * INNERq + h*DHq + c4];
        }
        __syncthreads();

        #pragma unroll 4
        for (int jj = 0; jj < 64; jj += 4) {
            float4 pa0 = *(const float4*)&Pt[(4*ty+0)*ATT_STRIDE + jj];
            float4 pa1 = *(const float4*)&Pt[(4*ty+1)*ATT_STRIDE + jj];
            float4 pa2 = *(const float4*)&Pt[(4*ty+2)*ATT_STRIDE + jj];
            float4 pa3 = *(const float4*)&Pt[(4*ty+3)*ATT_STRIDE + jj];
            float4 vb0 = *(const float4*)&KV[(jj+0)*ATT_STRIDE + 4*tx];
            float4 vb1 = *(const float4*)&KV[(jj+1)*ATT_STRIDE + 4*tx];
            float4 vb2 = *(const float4*)&KV[(jj+2)*ATT_STRIDE + 4*tx];
            float4 vb3 = *(const float4*)&KV[(jj+3)*ATT_STRIDE + 4*tx];
            acc[0][0] += pa0.x*vb0.x + pa0.y*vb1.x + pa0.z*vb2.x + pa0.w*vb3.x;
            acc[0][1] += pa0.x*vb0.y + pa0.y*vb1.y + pa0.z*vb2.y + pa0.w*vb3.y;
            acc[0][2] += pa0.x*vb0.z + pa0.y*vb1.z + pa0.z*vb2.z + pa0.w*vb3.z;
            acc[0][3] += pa0.x*vb0.w + pa0.y*vb1.w + pa0.z*vb2.w + pa0.w*vb3.w;
            acc[1][0] += pa1.x*vb0.x + pa1.y*vb1.x + pa1.z*vb2.x + pa1.w*vb3.x;
            acc[1][1] += pa1.x*vb0.y + pa1.y*vb1.y + pa1.z*vb2.y + pa1.w*vb3.y;
            acc[1][2] += pa1.x*vb0.z + pa1.y*vb1.z + pa1.z*vb2.z + pa1.w*vb3.z;
            acc[1][3] += pa1.x*vb0.w + pa1.y*vb1.w + pa1.z*vb2.w + pa1.w*vb3.w;
            acc[2][0] += pa2.x*vb0.x + pa2.y*vb1.x + pa2.z*vb2.x + pa2.w*vb3.x;
            acc[2][1] += pa2.x*vb0.y + pa2.y*vb1.y + pa2.z*vb2.y + pa2.w*vb3.y;
            acc[2][2] += pa2.x*vb0.z + pa2.y*vb1.z + pa2.z*vb2.z + pa2.w*vb3.z;
            acc[2][3] += pa2.x*vb0.w + pa2.y*vb1.w + pa2.z*vb2.w + pa2.w*vb3.w;
            acc[3][0] += pa3.x*vb0.x + pa3.y*vb1.x + pa3.z*vb2.x + pa3.w*vb3.x;
            acc[3][1] += pa3.x*vb0.y + pa3.y*vb1.y + pa3.z*vb2.y + pa3.w*vb3.y;
            acc[3][2] += pa3.x*vb0.z + pa3.y*vb1.z + pa3.z*vb2.z + pa3.w*vb3.z;
            acc[3][3] += pa3.x*vb0.w + pa3.y*vb1.w + pa3.z*vb2.w + pa3.w*vb3.w;
        }
    }

    #pragma unroll
    for (int a = 0; a < 4; a++)
        *(float4*)&Qt[(4*ty + a)*ATT_STRIDE + 4*tx] =
            make_float4(acc[a][0], acc[a][1], acc[a][2], acc[a][3]);
    __syncthreads();

    {
        int row = t >> 2, qd = t & 3;
        int i = i0 + row;
        float m    = m_row[row];
        float ssum = ssum_row[row];
        float denom = fmaxf(fabsf(ssum), __expf(-m)) + 1e-6f;
        float inv = 1.f / denom;
        float o[16];
        #pragma unroll
        for (int k4 = 0; k4 < 4; k4++) {
            float4 v = *(const float4*)&Qt[row*ATT_STRIDE + qd*16 + k4*4];
            o[k4*4+0] = v.x*inv; o[k4*4+1] = v.y*inv; o[k4*4+2] = v.z*inv; o[k4*4+3] = v.w*inv;
        }
        float mean = 0.f;
        #pragma unroll
        for (int d = 0; d < 16; d++) mean += o[d];
        mean += __shfl_xor_sync(0xffffffffu, mean, 1);
        mean += __shfl_xor_sync(0xffffffffu, mean, 2);
        mean *= (1.f / 64.f);
        float var = 0.f;
        #pragma unroll
        for (int d = 0; d < 16; d++) { float df = o[d] - mean; var += df * df; }
        var += __shfl_xor_sync(0xffffffffu, var, 1);
        var += __shfl_xor_sync(0xffffffffu, var, 2);
        var *= (1.f / 64.f);
        float rstd = rsqrtf(var + 1e-5f);
        size_t obase = ((size_t)(b*Sq + i)) * INNERq + h*DHq + qd*16;
        #pragma unroll
        for (int d = 0; d < 16; d++) {
            int c = h*DHq + qd*16 + d;
            float hn  = (o[d] - mean) * rstd * norm_w[c];
            float za  = g_z[obase + d];
            float sil = za / (1.f + __expf(-za));
            g_h[obase + d] = (hn + skipw[c] * g_xa[obase + d]) * sil;
        }
    }
}

// ---------------- launch ----------------
extern "C" void kernel_launch(void* const* d_in, const int* in_sizes, int n_in,
                              void* d_out, int out_size)
{
    const float* x      = (const float*)d_in[0];
    const float* W_up   = (const float*)d_in[1];
    const float* conv_w = (const float*)d_in[2];
    const float* conv_b = (const float*)d_in[3];
    const float* Wq     = (const float*)d_in[4];
    const float* Wk     = (const float*)d_in[5];
    const float* Wv     = (const float*)d_in[6];
    const float* W_i    = (const float*)d_in[7];
    const float* b_i    = (const float*)d_in[8];
    const float* W_f    = (const float*)d_in[9];
    const float* b_f    = (const float*)d_in[10];
    const float* norm_w = (const float*)d_in[11];
    const float* skipw  = (const float*)d_in[12];
    const float* W_down = (const float*)d_in[13];
    float* out = (float*)d_out;

    cudaFuncSetAttribute(attn_kernel,
                         cudaFuncAttributeMaxDynamicSharedMemorySize, ATT_SMEM_BYTES);

    gemm_nt<0><<<dim3(16, 64), 256>>>(x, W_up, nullptr, Cdim);
    fused_conv_qkv<<<Bq*Sq, 128>>>(conv_w, conv_b, Wq, Wk, Wv);
    gates_kernel<<<256, 256>>>(W_i, b_i, W_f, b_f);
    scan_kernel<<<Bq*NHq, 1024>>>();
    attn_kernel<<<512, 256, ATT_SMEM_BYTES>>>(norm_w, skipw);
    gemm_nt<1><<<dim3(4, 64), 256>>>(nullptr, W_down, out, INNERq);
}

// round 13
// speedup vs baseline: 1.1522x; 1.0284x over previous
#include <cuda_runtime.h>
#include <math.h>

#define Bq    4
#define Sq    1024
#define Cdim  256
#define INNERq 512
#define NHq   8
#define DHq   64

// ---------------- scratch (static __device__, no allocation) ----------------
__device__ float g_xm[Bq*Sq*INNERq];
__device__ float g_z [Bq*Sq*INNERq];
__device__ float g_xa[Bq*Sq*INNERq];
__device__ float g_q [Bq*Sq*INNERq];
__device__ float g_k [Bq*Sq*INNERq];
__device__ float g_v [Bq*Sq*INNERq];
__device__ float g_ig[Bq*NHq*Sq];
__device__ float g_fg[Bq*NHq*Sq];
__device__ float g_lc[Bq*NHq*Sq];
__device__ float g_h [Bq*Sq*INNERq];

// ---------------- NT GEMM: C[m,n] = sum_k A[m,k]*B[n,k] (R7 version, k-tile 16) ----------------
template<int MODE>
__global__ __launch_bounds__(256) void gemm_nt(
    const float* __restrict__ Aext, const float* __restrict__ Bm,
    float* __restrict__ outext, int Kd)
{
    __shared__ float As[16][65];
    __shared__ float Bs[16][65];
    const float* A = (MODE == 0) ? Aext : g_h;
    int tid = threadIdx.x;
    int m0 = blockIdx.y * 64, n0 = blockIdx.x * 64;
    int ty = tid >> 4, tx = tid & 15;
    int lr  = tid >> 2;
    int lc4 = (tid & 3) << 2;
    float acc[4][4] = {};
    const float* Ap = A  + (size_t)(m0 + lr) * Kd + lc4;
    const float* Bp = Bm + (size_t)(n0 + lr) * Kd + lc4;
    for (int k0 = 0; k0 < Kd; k0 += 16) {
        float4 av = *(const float4*)(Ap + k0);
        float4 bv = *(const float4*)(Bp + k0);
        As[lc4+0][lr] = av.x; As[lc4+1][lr] = av.y; As[lc4+2][lr] = av.z; As[lc4+3][lr] = av.w;
        Bs[lc4+0][lr] = bv.x; Bs[lc4+1][lr] = bv.y; Bs[lc4+2][lr] = bv.z; Bs[lc4+3][lr] = bv.w;
        __syncthreads();
        #pragma unroll
        for (int kk = 0; kk < 16; kk++) {
            float a[4], b[4];
            #pragma unroll
            for (int i = 0; i < 4; i++) { a[i] = As[kk][ty*4+i]; b[i] = Bs[kk][tx*4+i]; }
            #pragma unroll
            for (int i = 0; i < 4; i++)
                #pragma unroll
                for (int j = 0; j < 4; j++) acc[i][j] += a[i] * b[j];
        }
        __syncthreads();
    }
    #pragma unroll
    for (int i = 0; i < 4; i++) {
        int m = m0 + ty*4 + i;
        #pragma unroll
        for (int j = 0; j < 4; j++) {
            int n = n0 + tx*4 + j;
            if (MODE == 0) {
                if (n < INNERq) g_xm[(size_t)m * INNERq + n] = acc[i][j];
                else            g_z [(size_t)m * INNERq + (n - INNERq)] = acc[i][j];
            } else {
                outext[(size_t)m * Cdim + n] = acc[i][j];
            }
        }
    }
}

// ---------------- fused conv + silu + per-block qkv + gate dots (R7 fused version) ----------------
__global__ __launch_bounds__(128) void fused_conv_qkv_gates(
    const float* __restrict__ conv_w, const float* __restrict__ conv_b,
    const float* __restrict__ Wq, const float* __restrict__ Wk, const float* __restrict__ Wv,
    const float* __restrict__ W_i, const float* __restrict__ b_i,
    const float* __restrict__ W_f, const float* __restrict__ b_f)
{
    __shared__ float sh[3 * INNERq];
    int bs = blockIdx.x;
    int b = bs >> 10;
    int s = bs & 1023;
    int t = threadIdx.x;
    size_t rowbase = (size_t)bs * INNERq;

    float xm4[4], xa4[4];
    #pragma unroll
    for (int j = 0; j < 4; j++) {
        int c = t*4 + j;
        float a = conv_b[c];
        #pragma unroll
        for (int kk = 0; kk < 4; kk++) {
            int sp = s - 3 + kk;
            if (sp >= 0) a += g_xm[((size_t)(b*Sq + sp)) * INNERq + c] * conv_w[c*4 + kk];
        }
        float sg = 1.f / (1.f + __expf(-a));
        xa4[j] = a * sg;
        g_xa[rowbase + c] = xa4[j];
        xm4[j] = g_xm[rowbase + c];
    }

    float q4[4], k4[4], v4[4];
    #pragma unroll
    for (int o = 0; o < 4; o++) {
        float aq = 0.f, ak = 0.f, av = 0.f;
        #pragma unroll
        for (int d = 0; d < 4; d++) {
            aq += Wq[t*16 + o*4 + d] * xa4[d];
            ak += Wk[t*16 + o*4 + d] * xa4[d];
            av += Wv[t*16 + o*4 + d] * xm4[d];
        }
        q4[o] = aq; k4[o] = ak; v4[o] = av;
        sh[t*4 + o]            = aq;
        sh[INNERq + t*4 + o]   = ak;
        sh[2*INNERq + t*4 + o] = av;
    }
    *(float4*)&g_q[rowbase + t*4] = make_float4(q4[0], q4[1], q4[2], q4[3]);
    *(float4*)&g_k[rowbase + t*4] = make_float4(k4[0], k4[1], k4[2], k4[3]);
    *(float4*)&g_v[rowbase + t*4] = make_float4(v4[0], v4[1], v4[2], v4[3]);
    __syncthreads();

    int w = t >> 5, l = t & 31;
    #pragma unroll
    for (int g4 = 0; g4 < 4; g4++) {
        int g = w*4 + g4;
        int h = g & 7;
        const float* Wt = (g < 8 ? W_i : W_f) + h * 1536;
        float acc = 0.f;
        for (int idx = l*4; idx < 1536; idx += 128) {
            float4 sv = *(const float4*)&sh[idx];
            float4 wv = *(const float4*)&Wt[idx];
            acc += sv.x*wv.x + sv.y*wv.y + sv.z*wv.z + sv.w*wv.w;
        }
        #pragma unroll
        for (int o = 16; o; o >>= 1) acc += __shfl_xor_sync(0xffffffffu, acc, o);
        if (l == 0) {
            if (g < 8) g_ig[(size_t)(b*NHq + h) * Sq + s] = acc + b_i[h];
            else       g_fg[(size_t)(b*NHq + h) * Sq + s] = acc + b_f[h];
        }
    }
}

// ---------------- log-sigmoid + inclusive cumsum over S per (b,h) ----------------
__global__ __launch_bounds__(1024) void scan_kernel()
{
    int bh = blockIdx.x;
    int s = threadIdx.x;
    float x = g_fg[(size_t)bh * Sq + s];
    float lf = fminf(x, 0.f) - log1pf(expf(-fabsf(x)));
    __shared__ float sc[Sq];
    sc[s] = lf;
    __syncthreads();
    for (int off = 1; off < Sq; off <<= 1) {
        float tv = (s >= off) ? sc[s - off] : 0.f;
        __syncthreads();
        sc[s] += tv;
        __syncthreads();
    }
    g_lc[(size_t)bh * Sq + s] = sc[s];
}

// ---------------- attn v5: separate V buffer, 3 barriers/tile, K+V loads batched ----------------
#define ATT_STRIDE 68
#define ATT_SMEM_FLOATS (4*64*ATT_STRIDE + 7*64)
#define ATT_SMEM_BYTES  (ATT_SMEM_FLOATS*4)

__global__ __launch_bounds__(256) void attn_kernel(
    const float* __restrict__ norm_w, const float* __restrict__ skipw)
{
    extern __shared__ float sm[];
    float* Qt = sm;                       // [64][68] Q^T (reused as O)
    float* Kt = Qt + 64*ATT_STRIDE;       // [64][68] K^T (scaled)
    float* Vs = Kt + 64*ATT_STRIDE;       // [64][68] V row-major
    float* Pt = Vs + 64*ATT_STRIDE;       // [64][68] P row-major
    float* pm       = Pt + 64*ATT_STRIDE;
    float* ej       = pm + 64;
    float* m_row    = ej + 64;
    float* sc_row   = m_row + 64;
    float* Ei_row   = sc_row + 64;
    float* ssum_row = Ei_row + 64;
    float* lci_row  = ssum_row + 64;

    int xblk = blockIdx.x;
    int it = 15 - (xblk >> 5);
    int bh = xblk & 31;
    int b = bh >> 3, h = bh & 7;
    int i0 = it * 64;
    int t = threadIdx.x;
    int tx = t & 15, ty = t >> 4;

    #pragma unroll
    for (int e4 = 0; e4 < 4; e4++) {
        int e = t + 256 * e4;
        int row = e >> 4, c4 = (e & 15) << 2;
        float4 qv = *(const float4*)&g_q[((size_t)(b*Sq + i0 + row)) * INNERq + h*DHq + c4];
        Qt[(c4+0)*ATT_STRIDE + row] = qv.x;
        Qt[(c4+1)*ATT_STRIDE + row] = qv.y;
        Qt[(c4+2)*ATT_STRIDE + row] = qv.z;
        Qt[(c4+3)*ATT_STRIDE + row] = qv.w;
    }
    if (t < 64) {
        lci_row[t]  = g_lc[(size_t)bh*Sq + i0 + t];
        m_row[t]    = -3.4e38f;
        ssum_row[t] = 0.f;
    }

    float acc[4][4];
    #pragma unroll
    for (int a = 0; a < 4; a++)
        #pragma unroll
        for (int d = 0; d < 4; d++) acc[a][d] = 0.f;

    for (int jt = 0; jt <= it; jt++) {
        int j0 = jt * 64;
        __syncthreads();   // B1: prev tile consumed (init visible on first iter)

        // batched K (transposed+scaled) and V (row-major) loads — high MLP
        #pragma unroll
        for (int e4 = 0; e4 < 4; e4++) {
            int e = t + 256*e4;
            int row = e >> 4, c4 = (e & 15) << 2;
            size_t gb = ((size_t)(b*Sq + j0 + row)) * INNERq + h*DHq + c4;
            float4 kv = *(const float4*)&g_k[gb];
            float4 vv = *(const float4*)&g_v[gb];
            Kt[(c4+0)*ATT_STRIDE + row] = kv.x*0.125f;
            Kt[(c4+1)*ATT_STRIDE + row] = kv.y*0.125f;
            Kt[(c4+2)*ATT_STRIDE + row] = kv.z*0.125f;
            Kt[(c4+3)*ATT_STRIDE + row] = kv.w*0.125f;
            *(float4*)&Vs[row*ATT_STRIDE + c4] = vv;
        }
        if (t < 32) {
            int l = t;
            size_t gbase = (size_t)bh*Sq + j0;
            float a0 = g_ig[gbase + l]      - g_lc[gbase + l];
            float a1 = g_ig[gbase + 32 + l] - g_lc[gbase + 32 + l];
            float p0 = a0;
            #pragma unroll
            for (int off = 1; off < 32; off <<= 1) {
                float u = __shfl_up_sync(0xffffffffu, p0, off);
                if (l >= off) p0 = fmaxf(p0, u);
            }
            float max0 = __shfl_sync(0xffffffffu, p0, 31);
            float p1 = a1;
            #pragma unroll
            for (int off = 1; off < 32; off <<= 1) {
                float u = __shfl_up_sync(0xffffffffu, p1, off);
                if (l >= off) p1 = fmaxf(p1, u);
            }
            p1 = fmaxf(p1, max0);
            float pmAll = __shfl_sync(0xffffffffu, p1, 31);
            pm[l]      = p0;
            pm[32 + l] = p1;
            ej[l]      = __expf(a0 - pmAll);
            ej[32 + l] = __expf(a1 - pmAll);
            __syncwarp();
            #pragma unroll
            for (int half = 0; half < 2; half++) {
                int r = l + 32*half;
                int jm = i0 + r - j0 + 1;
                jm = jm > 64 ? 64 : jm;
                float mo = m_row[r];
                float rowmax = lci_row[r] + pm[jm-1];
                float mnew = fmaxf(mo, rowmax);
                float sc = __expf(mo - mnew);
                sc_row[r] = sc;
                Ei_row[r] = __expf(lci_row[r] + pmAll - mnew);
                m_row[r]  = mnew;
                ssum_row[r] *= sc;
            }
        }
        __syncthreads();   // B2: K/V/state ready

        #pragma unroll
        for (int a = 0; a < 4; a++) {
            float sc = sc_row[4*ty + a];
            #pragma unroll
            for (int d = 0; d < 4; d++) acc[a][d] *= sc;
        }

        // phase 1: S(4x4) = Q @ K^T
        float s[4][4];
        #pragma unroll
        for (int a = 0; a < 4; a++)
            #pragma unroll
            for (int c = 0; c < 4; c++) s[a][c] = 0.f;
        #pragma unroll 8
        for (int kk = 0; kk < 64; kk++) {
            float4 aq = *(const float4*)&Qt[kk*ATT_STRIDE + 4*ty];
            float4 bk = *(const float4*)&Kt[kk*ATT_STRIDE + 4*tx];
            s[0][0] += aq.x*bk.x; s[0][1] += aq.x*bk.y; s[0][2] += aq.x*bk.z; s[0][3] += aq.x*bk.w;
            s[1][0] += aq.y*bk.x; s[1][1] += aq.y*bk.y; s[1][2] += aq.y*bk.z; s[1][3] += aq.y*bk.w;
            s[2][0] += aq.z*bk.x; s[2][1] += aq.z*bk.y; s[2][2] += aq.z*bk.z; s[2][3] += aq.z*bk.w;
            s[3][0] += aq.w*bk.x; s[3][1] += aq.w*bk.y; s[3][2] += aq.w*bk.z; s[3][3] += aq.w*bk.w;
        }
        {
            float e0 = ej[4*tx], e1 = ej[4*tx+1], e2 = ej[4*tx+2], e3 = ej[4*tx+3];
            bool diag = (jt == it);
            int jg = j0 + 4*tx;
            #pragma unroll
            for (int a = 0; a < 4; a++) {
                int rr = 4*ty + a;
                float Ei = Ei_row[rr];
                float p0 = s[a][0]*Ei*e0;
                float p1 = s[a][1]*Ei*e1;
                float p2 = s[a][2]*Ei*e2;
                float p3 = s[a][3]*Ei*e3;
                if (diag) {
                    int ig = i0 + rr;
                    if (jg     > ig) p0 = 0.f;
                    if (jg + 1 > ig) p1 = 0.f;
                    if (jg + 2 > ig) p2 = 0.f;
                    if (jg + 3 > ig) p3 = 0.f;
                }
                *(float4*)&Pt[rr*ATT_STRIDE + 4*tx] = make_float4(p0, p1, p2, p3);
                float part = (p0 + p1) + (p2 + p3);
                part += __shfl_xor_sync(0xffffffffu, part, 1);
                part += __shfl_xor_sync(0xffffffffu, part, 2);
                part += __shfl_xor_sync(0xffffffffu, part, 4);
                part += __shfl_xor_sync(0xffffffffu, part, 8);
                if (tx == 0) ssum_row[rr] += part;
            }
        }
        __syncthreads();   // B3: P ready (V was loaded up front)

        // phase 2: O(4x4) += P @ V
        #pragma unroll 4
        for (int jj = 0; jj < 64; jj += 4) {
            float4 pa0 = *(const float4*)&Pt[(4*ty+0)*ATT_STRIDE + jj];
            float4 pa1 = *(const float4*)&Pt[(4*ty+1)*ATT_STRIDE + jj];
            float4 pa2 = *(const float4*)&Pt[(4*ty+2)*ATT_STRIDE + jj];
            float4 pa3 = *(const float4*)&Pt[(4*ty+3)*ATT_STRIDE + jj];
            float4 vb0 = *(const float4*)&Vs[(jj+0)*ATT_STRIDE + 4*tx];
            float4 vb1 = *(const float4*)&Vs[(jj+1)*ATT_STRIDE + 4*tx];
            float4 vb2 = *(const float4*)&Vs[(jj+2)*ATT_STRIDE + 4*tx];
            float4 vb3 = *(const float4*)&Vs[(jj+3)*ATT_STRIDE + 4*tx];
            acc[0][0] += pa0.x*vb0.x + pa0.y*vb1.x + pa0.z*vb2.x + pa0.w*vb3.x;
            acc[0][1] += pa0.x*vb0.y + pa0.y*vb1.y + pa0.z*vb2.y + pa0.w*vb3.y;
            acc[0][2] += pa0.x*vb0.z + pa0.y*vb1.z + pa0.z*vb2.z + pa0.w*vb3.z;
            acc[0][3] += pa0.x*vb0.w + pa0.y*vb1.w + pa0.z*vb2.w + pa0.w*vb3.w;
            acc[1][0] += pa1.x*vb0.x + pa1.y*vb1.x + pa1.z*vb2.x + pa1.w*vb3.x;
            acc[1][1] += pa1.x*vb0.y + pa1.y*vb1.y + pa1.z*vb2.y + pa1.w*vb3.y;
            acc[1][2] += pa1.x*vb0.z + pa1.y*vb1.z + pa1.z*vb2.z + pa1.w*vb3.z;
            acc[1][3] += pa1.x*vb0.w + pa1.y*vb1.w + pa1.z*vb2.w + pa1.w*vb3.w;
            acc[2][0] += pa2.x*vb0.x + pa2.y*vb1.x + pa2.z*vb2.x + pa2.w*vb3.x;
            acc[2][1] += pa2.x*vb0.y + pa2.y*vb1.y + pa2.z*vb2.y + pa2.w*vb3.y;
            acc[2][2] += pa2.x*vb0.z + pa2.y*vb1.z + pa2.z*vb2.z + pa2.w*vb3.z;
            acc[2][3] += pa2.x*vb0.w + pa2.y*vb1.w + pa2.z*vb2.w + pa2.w*vb3.w;
            acc[3][0] += pa3.x*vb0.x + pa3.y*vb1.x + pa3.z*vb2.x + pa3.w*vb3.x;
            acc[3][1] += pa3.x*vb0.y + pa3.y*vb1.y + pa3.z*vb2.y + pa3.w*vb3.y;
            acc[3][2] += pa3.x*vb0.z + pa3.y*vb1.z + pa3.z*vb2.z + pa3.w*vb3.z;
            acc[3][3] += pa3.x*vb0.w + pa3.y*vb1.w + pa3.z*vb2.w + pa3.w*vb3.w;
        }
    }

    __syncthreads();
    #pragma unroll
    for (int a = 0; a < 4; a++)
        *(float4*)&Qt[(4*ty + a)*ATT_STRIDE + 4*tx] =
            make_float4(acc[a][0], acc[a][1], acc[a][2], acc[a][3]);
    __syncthreads();

    {
        int row = t >> 2, qd = t & 3;
        int i = i0 + row;
        float m    = m_row[row];
        float ssum = ssum_row[row];
        float denom = fmaxf(fabsf(ssum), __expf(-m)) + 1e-6f;
        float inv = 1.f / denom;
        float o[16];
        #pragma unroll
        for (int k4 = 0; k4 < 4; k4++) {
            float4 v = *(const float4*)&Qt[row*ATT_STRIDE + qd*16 + k4*4];
            o[k4*4+0] = v.x*inv; o[k4*4+1] = v.y*inv; o[k4*4+2] = v.z*inv; o[k4*4+3] = v.w*inv;
        }
        float mean = 0.f;
        #pragma unroll
        for (int d = 0; d < 16; d++) mean += o[d];
        mean += __shfl_xor_sync(0xffffffffu, mean, 1);
        mean += __shfl_xor_sync(0xffffffffu, mean, 2);
        mean *= (1.f / 64.f);
        float var = 0.f;
        #pragma unroll
        for (int d = 0; d < 16; d++) { float df = o[d] - mean; var += df * df; }
        var += __shfl_xor_sync(0xffffffffu, var, 1);
        var += __shfl_xor_sync(0xffffffffu, var, 2);
        var *= (1.f / 64.f);
        float rstd = rsqrtf(var + 1e-5f);
        size_t obase = ((size_t)(b*Sq + i)) * INNERq + h*DHq + qd*16;
        #pragma unroll
        for (int d = 0; d < 16; d++) {
            int c = h*DHq + qd*16 + d;
            float hn  = (o[d] - mean) * rstd * norm_w[c];
            float za  = g_z[obase + d];
            float sil = za / (1.f + __expf(-za));
            g_h[obase + d] = (hn + skipw[c] * g_xa[obase + d]) * sil;
        }
    }
}

// ---------------- launch ----------------
extern "C" void kernel_launch(void* const* d_in, const int* in_sizes, int n_in,
                              void* d_out, int out_size)
{
    const float* x      = (const float*)d_in[0];
    const float* W_up   = (const float*)d_in[1];
    const float* conv_w = (const float*)d_in[2];
    const float* conv_b = (const float*)d_in[3];
    const float* Wq     = (const float*)d_in[4];
    const float* Wk     = (const float*)d_in[5];
    const float* Wv     = (const float*)d_in[6];
    const float* W_i    = (const float*)d_in[7];
    const float* b_i    = (const float*)d_in[8];
    const float* W_f    = (const float*)d_in[9];
    const float* b_f    = (const float*)d_in[10];
    const float* norm_w = (const float*)d_in[11];
    const float* skipw  = (const float*)d_in[12];
    const float* W_down = (const float*)d_in[13];
    float* out = (float*)d_out;

    cudaFuncSetAttribute(attn_kernel,
                         cudaFuncAttributeMaxDynamicSharedMemorySize, ATT_SMEM_BYTES);

    gemm_nt<0><<<dim3(16, 64), 256>>>(x, W_up, nullptr, Cdim);
    fused_conv_qkv_gates<<<Bq*Sq, 128>>>(conv_w, conv_b, Wq, Wk, Wv, W_i, b_i, W_f, b_f);
    scan_kernel<<<Bq*NHq, 1024>>>();
    attn_kernel<<<512, 256, ATT_SMEM_BYTES>>>(norm_w, skipw);
    gemm_nt<1><<<dim3(4, 64), 256>>>(nullptr, W_down, out, INNERq);
}

// round 14
// speedup vs baseline: 1.2348x; 1.0717x over previous
#include <cuda_runtime.h>
#include <math.h>

#define Bq    4
#define Sq    1024
#define Cdim  256
#define INNERq 512
#define NHq   8
#define DHq   64

// ---------------- scratch (static __device__, no allocation) ----------------
__device__ float g_xm[Bq*Sq*INNERq];
__device__ float g_z [Bq*Sq*INNERq];
__device__ float g_xa[Bq*Sq*INNERq];
__device__ float g_q [Bq*Sq*INNERq];
__device__ float g_k [Bq*Sq*INNERq];
__device__ float g_v [Bq*Sq*INNERq];
__device__ float g_ig[Bq*NHq*Sq];
__device__ float g_fg[Bq*NHq*Sq];
__device__ float g_lc[Bq*NHq*Sq];
__device__ float g_h [Bq*Sq*INNERq];

// ---------------- NT GEMM: C[m,n] = sum_k A[m,k]*B[n,k] (float4 smem reads) ----------------
template<int MODE>
__global__ __launch_bounds__(256) void gemm_nt(
    const float* __restrict__ Aext, const float* __restrict__ Bm,
    float* __restrict__ outext, int Kd)
{
    __shared__ float As[16][68];   // stride 272B = 17*16: float4-aligned rows
    __shared__ float Bs[16][68];
    const float* A = (MODE == 0) ? Aext : g_h;
    int tid = threadIdx.x;
    int m0 = blockIdx.y * 64, n0 = blockIdx.x * 64;
    int ty = tid >> 4, tx = tid & 15;
    int lr  = tid >> 2;
    int lc4 = (tid & 3) << 2;
    float acc[4][4] = {};
    const float* Ap = A  + (size_t)(m0 + lr) * Kd + lc4;
    const float* Bp = Bm + (size_t)(n0 + lr) * Kd + lc4;
    for (int k0 = 0; k0 < Kd; k0 += 16) {
        float4 av = *(const float4*)(Ap + k0);
        float4 bv = *(const float4*)(Bp + k0);
        As[lc4+0][lr] = av.x; As[lc4+1][lr] = av.y; As[lc4+2][lr] = av.z; As[lc4+3][lr] = av.w;
        Bs[lc4+0][lr] = bv.x; Bs[lc4+1][lr] = bv.y; Bs[lc4+2][lr] = bv.z; Bs[lc4+3][lr] = bv.w;
        __syncthreads();
        #pragma unroll
        for (int kk = 0; kk < 16; kk++) {
            float4 a = *(const float4*)&As[kk][ty*4];
            float4 b = *(const float4*)&Bs[kk][tx*4];
            acc[0][0] += a.x*b.x; acc[0][1] += a.x*b.y; acc[0][2] += a.x*b.z; acc[0][3] += a.x*b.w;
            acc[1][0] += a.y*b.x; acc[1][1] += a.y*b.y; acc[1][2] += a.y*b.z; acc[1][3] += a.y*b.w;
            acc[2][0] += a.z*b.x; acc[2][1] += a.z*b.y; acc[2][2] += a.z*b.z; acc[2][3] += a.z*b.w;
            acc[3][0] += a.w*b.x; acc[3][1] += a.w*b.y; acc[3][2] += a.w*b.z; acc[3][3] += a.w*b.w;
        }
        __syncthreads();
    }
    #pragma unroll
    for (int i = 0; i < 4; i++) {
        int m = m0 + ty*4 + i;
        #pragma unroll
        for (int j = 0; j < 4; j++) {
            int n = n0 + tx*4 + j;
            if (MODE == 0) {
                if (n < INNERq) g_xm[(size_t)m * INNERq + n] = acc[i][j];
                else            g_z [(size_t)m * INNERq + (n - INNERq)] = acc[i][j];
            } else {
                outext[(size_t)m * Cdim + n] = acc[i][j];
            }
        }
    }
}

// ---------------- fused conv + silu + per-block qkv + gate dots ----------------
__global__ __launch_bounds__(128) void fused_conv_qkv_gates(
    const float* __restrict__ conv_w, const float* __restrict__ conv_b,
    const float* __restrict__ Wq, const float* __restrict__ Wk, const float* __restrict__ Wv,
    const float* __restrict__ W_i, const float* __restrict__ b_i,
    const float* __restrict__ W_f, const float* __restrict__ b_f)
{
    __shared__ float sh[3 * INNERq];
    int bs = blockIdx.x;
    int b = bs >> 10;
    int s = bs & 1023;
    int t = threadIdx.x;
    size_t rowbase = (size_t)bs * INNERq;

    float xm4[4], xa4[4];
    #pragma unroll
    for (int j = 0; j < 4; j++) {
        int c = t*4 + j;
        float a = conv_b[c];
        #pragma unroll
        for (int kk = 0; kk < 4; kk++) {
            int sp = s - 3 + kk;
            if (sp >= 0) a += g_xm[((size_t)(b*Sq + sp)) * INNERq + c] * conv_w[c*4 + kk];
        }
        float sg = 1.f / (1.f + __expf(-a));
        xa4[j] = a * sg;
        g_xa[rowbase + c] = xa4[j];
        xm4[j] = g_xm[rowbase + c];
    }

    float q4[4], k4[4], v4[4];
    #pragma unroll
    for (int o = 0; o < 4; o++) {
        float aq = 0.f, ak = 0.f, av = 0.f;
        #pragma unroll
        for (int d = 0; d < 4; d++) {
            aq += Wq[t*16 + o*4 + d] * xa4[d];
            ak += Wk[t*16 + o*4 + d] * xa4[d];
            av += Wv[t*16 + o*4 + d] * xm4[d];
        }
        q4[o] = aq; k4[o] = ak; v4[o] = av;
        sh[t*4 + o]            = aq;
        sh[INNERq + t*4 + o]   = ak;
        sh[2*INNERq + t*4 + o] = av;
    }
    *(float4*)&g_q[rowbase + t*4] = make_float4(q4[0], q4[1], q4[2], q4[3]);
    *(float4*)&g_k[rowbase + t*4] = make_float4(k4[0], k4[1], k4[2], k4[3]);
    *(float4*)&g_v[rowbase + t*4] = make_float4(v4[0], v4[1], v4[2], v4[3]);
    __syncthreads();

    int w = t >> 5, l = t & 31;
    #pragma unroll
    for (int g4 = 0; g4 < 4; g4++) {
        int g = w*4 + g4;
        int h = g & 7;
        const float* Wt = (g < 8 ? W_i : W_f) + h * 1536;
        float acc = 0.f;
        for (int idx = l*4; idx < 1536; idx += 128) {
            float4 sv = *(const float4*)&sh[idx];
            float4 wv = *(const float4*)&Wt[idx];
            acc += sv.x*wv.x + sv.y*wv.y + sv.z*wv.z + sv.w*wv.w;
        }
        #pragma unroll
        for (int o = 16; o; o >>= 1) acc += __shfl_xor_sync(0xffffffffu, acc, o);
        if (l == 0) {
            if (g < 8) g_ig[(size_t)(b*NHq + h) * Sq + s] = acc + b_i[h];
            else       g_fg[(size_t)(b*NHq + h) * Sq + s] = acc + b_f[h];
        }
    }
}

// ---------------- log-sigmoid + inclusive cumsum over S per (b,h) ----------------
__global__ __launch_bounds__(1024) void scan_kernel()
{
    int bh = blockIdx.x;
    int s = threadIdx.x;
    float x = g_fg[(size_t)bh * Sq + s];
    float lf = fminf(x, 0.f) - log1pf(expf(-fabsf(x)));
    __shared__ float sc[Sq];
    sc[s] = lf;
    __syncthreads();
    for (int off = 1; off < Sq; off <<= 1) {
        float tv = (s >= off) ? sc[s - off] : 0.f;
        __syncthreads();
        sc[s] += tv;
        __syncthreads();
    }
    g_lc[(size_t)bh * Sq + s] = sc[s];
}

// ---------------- attn v6: 32-row tiles, 1024 blocks, 128 threads (tail-balance) ----------------
// Row-tile = 32 q-rows; j-tiles of 64. Micro 4x4 (ty 0..7 rows, tx 0..15 cols).
#define AST   68          // K/V/P row stride
#define QST   36          // Qt [dim][row] stride (32 rows + pad)
#define ATT_SMEM_FLOATS (64*QST + 2*64*AST + 32*AST + 2*64 + 5*32)
#define ATT_SMEM_BYTES  (ATT_SMEM_FLOATS*4)

__global__ __launch_bounds__(128) void attn_kernel(
    const float* __restrict__ norm_w, const float* __restrict__ skipw)
{
    extern __shared__ float sm[];
    float* Qt = sm;                   // [64][36]  Q^T [dim][row]
    float* Kt = Qt + 64*QST;          // [64][68]  K^T [dim][j] scaled
    float* Vs = Kt + 64*AST;          // [64][68]  V row-major (reused for O staging)
    float* Pt = Vs + 64*AST;          // [32][68]  P row-major
    float* pm       = Pt + 32*AST;    // [64]
    float* ej       = pm + 64;        // [64]
    float* m_row    = ej + 64;        // [32]
    float* sc_row   = m_row + 32;
    float* Ei_row   = sc_row + 32;
    float* ssum_row = Ei_row + 32;
    float* lci_row  = ssum_row + 32;

    int xblk = blockIdx.x;            // 0..1023
    int r32 = 31 - (xblk >> 5);       // biggest row-tiles first
    int bh = xblk & 31;
    int b = bh >> 3, h = bh & 7;
    int i0 = r32 * 32;
    int t = threadIdx.x;              // 0..127
    int tx = t & 15, ty = t >> 4;     // ty 0..7

    // load Q^T (32 rows x 64 dims): 512 float4 over 128 threads
    #pragma unroll
    for (int e4 = 0; e4 < 4; e4++) {
        int e = t + 128 * e4;
        int row = e >> 4, c4 = (e & 15) << 2;
        float4 qv = *(const float4*)&g_q[((size_t)(b*Sq + i0 + row)) * INNERq + h*DHq + c4];
        Qt[(c4+0)*QST + row] = qv.x;
        Qt[(c4+1)*QST + row] = qv.y;
        Qt[(c4+2)*QST + row] = qv.z;
        Qt[(c4+3)*QST + row] = qv.w;
    }
    if (t < 32) {
        lci_row[t]  = g_lc[(size_t)bh*Sq + i0 + t];
        m_row[t]    = -3.4e38f;
        ssum_row[t] = 0.f;
    }

    float acc[4][4];
    #pragma unroll
    for (int a = 0; a < 4; a++)
        #pragma unroll
        for (int d = 0; d < 4; d++) acc[a][d] = 0.f;

    int ntiles = (r32 >> 1) + 1;
    for (int jt = 0; jt < ntiles; jt++) {
        int j0 = jt * 64;
        __syncthreads();   // prev tile consumed / init visible

        // K^T (scaled) + V loads: 1024 float4 each over 128 threads
        #pragma unroll
        for (int e4 = 0; e4 < 8; e4++) {
            int e = t + 128*e4;
            int row = e >> 4, c4 = (e & 15) << 2;
            size_t gb = ((size_t)(b*Sq + j0 + row)) * INNERq + h*DHq + c4;
            float4 kv = *(const float4*)&g_k[gb];
            float4 vv = *(const float4*)&g_v[gb];
            Kt[(c4+0)*AST + row] = kv.x*0.125f;
            Kt[(c4+1)*AST + row] = kv.y*0.125f;
            Kt[(c4+2)*AST + row] = kv.z*0.125f;
            Kt[(c4+3)*AST + row] = kv.w*0.125f;
            *(float4*)&Vs[row*AST + c4] = vv;
        }
        if (t < 32) {
            int l = t;
            size_t gbase = (size_t)bh*Sq + j0;
            float a0 = g_ig[gbase + l]      - g_lc[gbase + l];
            float a1 = g_ig[gbase + 32 + l] - g_lc[gbase + 32 + l];
            float p0 = a0;
            #pragma unroll
            for (int off = 1; off < 32; off <<= 1) {
                float u = __shfl_up_sync(0xffffffffu, p0, off);
                if (l >= off) p0 = fmaxf(p0, u);
            }
            float max0 = __shfl_sync(0xffffffffu, p0, 31);
            float p1 = a1;
            #pragma unroll
            for (int off = 1; off < 32; off <<= 1) {
                float u = __shfl_up_sync(0xffffffffu, p1, off);
                if (l >= off) p1 = fmaxf(p1, u);
            }
            p1 = fmaxf(p1, max0);
            float pmAll = __shfl_sync(0xffffffffu, p1, 31);
            pm[l]      = p0;
            pm[32 + l] = p1;
            ej[l]      = __expf(a0 - pmAll);
            ej[32 + l] = __expf(a1 - pmAll);
            __syncwarp();
            // per-row state for the 32 rows
            int r = l;
            int jm = i0 + r - j0 + 1;
            jm = jm > 64 ? 64 : jm;          // >=1 always (j0 <= i0)
            float mo = m_row[r];
            float rowmax = lci_row[r] + pm[jm-1];
            float mnew = fmaxf(mo, rowmax);
            float sc = __expf(mo - mnew);
            sc_row[r] = sc;
            Ei_row[r] = __expf(lci_row[r] + pmAll - mnew);
            m_row[r]  = mnew;
            ssum_row[r] *= sc;
        }
        __syncthreads();

        #pragma unroll
        for (int a = 0; a < 4; a++) {
            float sc = sc_row[4*ty + a];
            #pragma unroll
            for (int d = 0; d < 4; d++) acc[a][d] *= sc;
        }

        // phase 1: S(4x4) = Q @ K^T over 64 dims
        float s[4][4];
        #pragma unroll
        for (int a = 0; a < 4; a++)
            #pragma unroll
            for (int c = 0; c < 4; c++) s[a][c] = 0.f;
        #pragma unroll 8
        for (int kk = 0; kk < 64; kk++) {
            float4 aq = *(const float4*)&Qt[kk*QST + 4*ty];
            float4 bk = *(const float4*)&Kt[kk*AST + 4*tx];
            s[0][0] += aq.x*bk.x; s[0][1] += aq.x*bk.y; s[0][2] += aq.x*bk.z; s[0][3] += aq.x*bk.w;
            s[1][0] += aq.y*bk.x; s[1][1] += aq.y*bk.y; s[1][2] += aq.y*bk.z; s[1][3] += aq.y*bk.w;
            s[2][0] += aq.z*bk.x; s[2][1] += aq.z*bk.y; s[2][2] += aq.z*bk.z; s[2][3] += aq.z*bk.w;
            s[3][0] += aq.w*bk.x; s[3][1] += aq.w*bk.y; s[3][2] += aq.w*bk.z; s[3][3] += aq.w*bk.w;
        }
        {
            float e0 = ej[4*tx], e1 = ej[4*tx+1], e2 = ej[4*tx+2], e3 = ej[4*tx+3];
            bool diag = (jt == ntiles - 1);
            int jg = j0 + 4*tx;
            #pragma unroll
            for (int a = 0; a < 4; a++) {
                int rr = 4*ty + a;
                float Ei = Ei_row[rr];
                float p0 = s[a][0]*Ei*e0;
                float p1 = s[a][1]*Ei*e1;
                float p2 = s[a][2]*Ei*e2;
                float p3 = s[a][3]*Ei*e3;
                if (diag) {
                    int ig = i0 + rr;
                    if (jg     > ig) p0 = 0.f;
                    if (jg + 1 > ig) p1 = 0.f;
                    if (jg + 2 > ig) p2 = 0.f;
                    if (jg + 3 > ig) p3 = 0.f;
                }
                *(float4*)&Pt[rr*AST + 4*tx] = make_float4(p0, p1, p2, p3);
                float part = (p0 + p1) + (p2 + p3);
                part += __shfl_xor_sync(0xffffffffu, part, 1);
                part += __shfl_xor_sync(0xffffffffu, part, 2);
                part += __shfl_xor_sync(0xffffffffu, part, 4);
                part += __shfl_xor_sync(0xffffffffu, part, 8);
                if (tx == 0) ssum_row[rr] += part;
            }
        }
        __syncthreads();   // P ready (V already loaded)

        // phase 2: O(4x4) += P @ V
        #pragma unroll 4
        for (int jj = 0; jj < 64; jj += 4) {
            float4 pa0 = *(const float4*)&Pt[(4*ty+0)*AST + jj];
            float4 pa1 = *(const float4*)&Pt[(4*ty+1)*AST + jj];
            float4 pa2 = *(const float4*)&Pt[(4*ty+2)*AST + jj];
            float4 pa3 = *(const float4*)&Pt[(4*ty+3)*AST + jj];
            float4 vb0 = *(const float4*)&Vs[(jj+0)*AST + 4*tx];
            float4 vb1 = *(const float4*)&Vs[(jj+1)*AST + 4*tx];
            float4 vb2 = *(const float4*)&Vs[(jj+2)*AST + 4*tx];
            float4 vb3 = *(const float4*)&Vs[(jj+3)*AST + 4*tx];
            acc[0][0] += pa0.x*vb0.x + pa0.y*vb1.x + pa0.z*vb2.x + pa0.w*vb3.x;
            acc[0][1] += pa0.x*vb0.y + pa0.y*vb1.y + pa0.z*vb2.y + pa0.w*vb3.y;
            acc[0][2] += pa0.x*vb0.z + pa0.y*vb1.z + pa0.z*vb2.z + pa0.w*vb3.z;
            acc[0][3] += pa0.x*vb0.w + pa0.y*vb1.w + pa0.z*vb2.w + pa0.w*vb3.w;
            acc[1][0] += pa1.x*vb0.x + pa1.y*vb1.x + pa1.z*vb2.x + pa1.w*vb3.x;
            acc[1][1] += pa1.x*vb0.y + pa1.y*vb1.y + pa1.z*vb2.y + pa1.w*vb3.y;
            acc[1][2] += pa1.x*vb0.z + pa1.y*vb1.z + pa1.z*vb2.z + pa1.w*vb3.z;
            acc[1][3] += pa1.x*vb0.w + pa1.y*vb1.w + pa1.z*vb2.w + pa1.w*vb3.w;
            acc[2][0] += pa2.x*vb0.x + pa2.y*vb1.x + pa2.z*vb2.x + pa2.w*vb3.x;
            acc[2][1] += pa2.x*vb0.y + pa2.y*vb1.y + pa2.z*vb2.y + pa2.w*vb3.y;
            acc[2][2] += pa2.x*vb0.z + pa2.y*vb1.z + pa2.z*vb2.z + pa2.w*vb3.z;
            acc[2][3] += pa2.x*vb0.w + pa2.y*vb1.w + pa2.z*vb2.w + pa2.w*vb3.w;
            acc[3][0] += pa3.x*vb0.x + pa3.y*vb1.x + pa3.z*vb2.x + pa3.w*vb3.x;
            acc[3][1] += pa3.x*vb0.y + pa3.y*vb1.y + pa3.z*vb2.y + pa3.w*vb3.y;
            acc[3][2] += pa3.x*vb0.z + pa3.y*vb1.z + pa3.z*vb2.z + pa3.w*vb3.z;
            acc[3][3] += pa3.x*vb0.w + pa3.y*vb1.w + pa3.z*vb2.w + pa3.w*vb3.w;
        }
    }

    __syncthreads();
    // stage O (32 rows x 64 dims) into Vs
    #pragma unroll
    for (int a = 0; a < 4; a++)
        *(float4*)&Vs[(4*ty + a)*AST + 4*tx] =
            make_float4(acc[a][0], acc[a][1], acc[a][2], acc[a][3]);
    __syncthreads();

    // LN + skip + silu(z): thread = (row = t>>2 in 0..31, quarter qd = t&3)
    {
        int row = t >> 2, qd = t & 3;
        int i = i0 + row;
        float m    = m_row[row];
        float ssum = ssum_row[row];
        float denom = fmaxf(fabsf(ssum), __expf(-m)) + 1e-6f;
        float inv = 1.f / denom;
        float o[16];
        #pragma unroll
        for (int k4 = 0; k4 < 4; k4++) {
            float4 v = *(const float4*)&Vs[row*AST + qd*16 + k4*4];
            o[k4*4+0] = v.x*inv; o[k4*4+1] = v.y*inv; o[k4*4+2] = v.z*inv; o[k4*4+3] = v.w*inv;
        }
        float mean = 0.f;
        #pragma unroll
        for (int d = 0; d < 16; d++) mean += o[d];
        mean += __shfl_xor_sync(0xffffffffu, mean, 1);
        mean += __shfl_xor_sync(0xffffffffu, mean, 2);
        mean *= (1.f / 64.f);
        float var = 0.f;
        #pragma unroll
        for (int d = 0; d < 16; d++) { float df = o[d] - mean; var += df * df; }
        var += __shfl_xor_sync(0xffffffffu, var, 1);
        var += __shfl_xor_sync(0xffffffffu, var, 2);
        var *= (1.f / 64.f);
        float rstd = rsqrtf(var + 1e-5f);
        size_t obase = ((size_t)(b*Sq + i)) * INNERq + h*DHq + qd*16;
        #pragma unroll
        for (int d = 0; d < 16; d++) {
            int c = h*DHq + qd*16 + d;
            float hn  = (o[d] - mean) * rstd * norm_w[c];
            float za  = g_z[obase + d];
            float sil = za / (1.f + __expf(-za));
            g_h[obase + d] = (hn + skipw[c] * g_xa[obase + d]) * sil;
        }
    }
}

// ---------------- launch ----------------
extern "C" void kernel_launch(void* const* d_in, const int* in_sizes, int n_in,
                              void* d_out, int out_size)
{
    const float* x      = (const float*)d_in[0];
    const float* W_up   = (const float*)d_in[1];
    const float* conv_w = (const float*)d_in[2];
    const float* conv_b = (const float*)d_in[3];
    const float* Wq     = (const float*)d_in[4];
    const float* Wk     = (const float*)d_in[5];
    const float* Wv     = (const float*)d_in[6];
    const float* W_i    = (const float*)d_in[7];
    const float* b_i    = (const float*)d_in[8];
    const float* W_f    = (const float*)d_in[9];
    const float* b_f    = (const float*)d_in[10];
    const float* norm_w = (const float*)d_in[11];
    const float* skipw  = (const float*)d_in[12];
    const float* W_down = (const float*)d_in[13];
    float* out = (float*)d_out;

    cudaFuncSetAttribute(attn_kernel,
                         cudaFuncAttributeMaxDynamicSharedMemorySize, ATT_SMEM_BYTES);

    gemm_nt<0><<<dim3(16, 64), 256>>>(x, W_up, nullptr, Cdim);
    fused_conv_qkv_gates<<<Bq*Sq, 128>>>(conv_w, conv_b, Wq, Wk, Wv, W_i, b_i, W_f, b_f);
    scan_kernel<<<Bq*NHq, 1024>>>();
    attn_kernel<<<1024, 128, ATT_SMEM_BYTES>>>(norm_w, skipw);
    gemm_nt<1><<<dim3(4, 64), 256>>>(nullptr, W_down, out, INNERq);
}

// round 15
// speedup vs baseline: 1.2669x; 1.0260x over previous
#include <cuda_runtime.h>
#include <math.h>

#define Bq    4
#define Sq    1024
#define Cdim  256
#define INNERq 512
#define NHq   8
#define DHq   64

// ---------------- scratch (static __device__, no allocation) ----------------
__device__ float g_xm[Bq*Sq*INNERq];
__device__ float g_z [Bq*Sq*INNERq];
__device__ float g_xa[Bq*Sq*INNERq];
__device__ float g_q [Bq*Sq*INNERq];
__device__ float g_k [Bq*Sq*INNERq];
__device__ float g_v [Bq*Sq*INNERq];
__device__ float g_ig[Bq*NHq*Sq];
__device__ float g_fg[Bq*NHq*Sq];
__device__ float g_lc[Bq*NHq*Sq];
__device__ float g_h [Bq*Sq*INNERq];

// ---------------- up GEMM: 128x128 tiles, 8x8 micro (1 B/FMA) ----------------
// C[m,n] = sum_k x[m,k]*W_up[n,k]; n<512 -> g_xm, else g_z
__global__ __launch_bounds__(256) void gemm_up(
    const float* __restrict__ A, const float* __restrict__ Bm)
{
    __shared__ float As[16][136];   // [k][m], rows 544B = 34*16 aligned
    __shared__ float Bs[16][136];   // [k][n]
    int tid = threadIdx.x;
    int m0 = blockIdx.y * 128, n0 = blockIdx.x * 128;
    int ty = tid >> 4, tx = tid & 15;
    int lr = tid >> 1, lc8 = (tid & 1) << 3;
    float acc[8][8] = {};
    const float* Ap = A  + (size_t)(m0 + lr) * Cdim + lc8;
    const float* Bp = Bm + (size_t)(n0 + lr) * Cdim + lc8;
    for (int k0 = 0; k0 < Cdim; k0 += 16) {
        float4 a0 = *(const float4*)(Ap + k0);
        float4 a1 = *(const float4*)(Ap + k0 + 4);
        float4 b0 = *(const float4*)(Bp + k0);
        float4 b1 = *(const float4*)(Bp + k0 + 4);
        As[lc8+0][lr] = a0.x; As[lc8+1][lr] = a0.y; As[lc8+2][lr] = a0.z; As[lc8+3][lr] = a0.w;
        As[lc8+4][lr] = a1.x; As[lc8+5][lr] = a1.y; As[lc8+6][lr] = a1.z; As[lc8+7][lr] = a1.w;
        Bs[lc8+0][lr] = b0.x; Bs[lc8+1][lr] = b0.y; Bs[lc8+2][lr] = b0.z; Bs[lc8+3][lr] = b0.w;
        Bs[lc8+4][lr] = b1.x; Bs[lc8+5][lr] = b1.y; Bs[lc8+6][lr] = b1.z; Bs[lc8+7][lr] = b1.w;
        __syncthreads();
        #pragma unroll
        for (int kk = 0; kk < 16; kk++) {
            float4 x0 = *(const float4*)&As[kk][8*ty];
            float4 x1 = *(const float4*)&As[kk][8*ty + 4];
            float4 y0 = *(const float4*)&Bs[kk][8*tx];
            float4 y1 = *(const float4*)&Bs[kk][8*tx + 4];
            float av[8] = {x0.x,x0.y,x0.z,x0.w,x1.x,x1.y,x1.z,x1.w};
            float bv[8] = {y0.x,y0.y,y0.z,y0.w,y1.x,y1.y,y1.z,y1.w};
            #pragma unroll
            for (int i = 0; i < 8; i++)
                #pragma unroll
                for (int j = 0; j < 8; j++) acc[i][j] += av[i] * bv[j];
        }
        __syncthreads();
    }
    float* dst; int nn0;
    if (n0 < INNERq) { dst = g_xm; nn0 = n0; } else { dst = g_z; nn0 = n0 - INNERq; }
    #pragma unroll
    for (int i = 0; i < 8; i++) {
        size_t base = (size_t)(m0 + 8*ty + i) * INNERq + nn0 + 8*tx;
        *(float4*)&dst[base]     = make_float4(acc[i][0], acc[i][1], acc[i][2], acc[i][3]);
        *(float4*)&dst[base + 4] = make_float4(acc[i][4], acc[i][5], acc[i][6], acc[i][7]);
    }
}

// ---------------- down GEMM: 128x64 tiles, 8x4 micro (1.5 B/FMA) ----------------
// out[m,n] = sum_k g_h[m,k]*W_down[n,k]
__global__ __launch_bounds__(256) void gemm_down(
    const float* __restrict__ Bm, float* __restrict__ outext)
{
    __shared__ float As[16][136];   // [k][m] 128 rows
    __shared__ float Bs[16][68];    // [k][n] 64 rows
    int tid = threadIdx.x;
    int m0 = blockIdx.y * 128, n0 = blockIdx.x * 64;
    int ty = tid >> 4, tx = tid & 15;
    int lra = tid >> 1, lc8 = (tid & 1) << 3;   // A: 128 rows x 2 halves
    int lrb = tid >> 2, lc4 = (tid & 3) << 2;   // B: 64 rows x 4 quarters
    float acc[8][4] = {};
    const float* Ap = g_h + (size_t)(m0 + lra) * INNERq + lc8;
    const float* Bp = Bm  + (size_t)(n0 + lrb) * INNERq + lc4;
    for (int k0 = 0; k0 < INNERq; k0 += 16) {
        float4 a0 = *(const float4*)(Ap + k0);
        float4 a1 = *(const float4*)(Ap + k0 + 4);
        float4 b0 = *(const float4*)(Bp + k0);
        As[lc8+0][lra] = a0.x; As[lc8+1][lra] = a0.y; As[lc8+2][lra] = a0.z; As[lc8+3][lra] = a0.w;
        As[lc8+4][lra] = a1.x; As[lc8+5][lra] = a1.y; As[lc8+6][lra] = a1.z; As[lc8+7][lra] = a1.w;
        Bs[lc4+0][lrb] = b0.x; Bs[lc4+1][lrb] = b0.y; Bs[lc4+2][lrb] = b0.z; Bs[lc4+3][lrb] = b0.w;
        __syncthreads();
        #pragma unroll
        for (int kk = 0; kk < 16; kk++) {
            float4 x0 = *(const float4*)&As[kk][8*ty];
            float4 x1 = *(const float4*)&As[kk][8*ty + 4];
            float4 y0 = *(const float4*)&Bs[kk][4*tx];
            float av[8] = {x0.x,x0.y,x0.z,x0.w,x1.x,x1.y,x1.z,x1.w};
            #pragma unroll
            for (int i = 0; i < 8; i++) {
                acc[i][0] += av[i]*y0.x; acc[i][1] += av[i]*y0.y;
                acc[i][2] += av[i]*y0.z; acc[i][3] += av[i]*y0.w;
            }
        }
        __syncthreads();
    }
    #pragma unroll
    for (int i = 0; i < 8; i++) {
        size_t base = (size_t)(m0 + 8*ty + i) * Cdim + n0 + 4*tx;
        *(float4*)&outext[base] = make_float4(acc[i][0], acc[i][1], acc[i][2], acc[i][3]);
    }
}

// ---------------- fused conv + silu + per-block qkv + gate dots ----------------
__global__ __launch_bounds__(128) void fused_conv_qkv_gates(
    const float* __restrict__ conv_w, const float* __restrict__ conv_b,
    const float* __restrict__ Wq, const float* __restrict__ Wk, const float* __restrict__ Wv,
    const float* __restrict__ W_i, const float* __restrict__ b_i,
    const float* __restrict__ W_f, const float* __restrict__ b_f)
{
    __shared__ float sh[3 * INNERq];
    int bs = blockIdx.x;
    int b = bs >> 10;
    int s = bs & 1023;
    int t = threadIdx.x;
    size_t rowbase = (size_t)bs * INNERq;

    float xm4[4], xa4[4];
    #pragma unroll
    for (int j = 0; j < 4; j++) {
        int c = t*4 + j;
        float a = conv_b[c];
        #pragma unroll
        for (int kk = 0; kk < 4; kk++) {
            int sp = s - 3 + kk;
            if (sp >= 0) a += g_xm[((size_t)(b*Sq + sp)) * INNERq + c] * conv_w[c*4 + kk];
        }
        float sg = 1.f / (1.f + __expf(-a));
        xa4[j] = a * sg;
        g_xa[rowbase + c] = xa4[j];
        xm4[j] = g_xm[rowbase + c];
    }

    float q4[4], k4[4], v4[4];
    #pragma unroll
    for (int o = 0; o < 4; o++) {
        float aq = 0.f, ak = 0.f, av = 0.f;
        #pragma unroll
        for (int d = 0; d < 4; d++) {
            aq += Wq[t*16 + o*4 + d] * xa4[d];
            ak += Wk[t*16 + o*4 + d] * xa4[d];
            av += Wv[t*16 + o*4 + d] * xm4[d];
        }
        q4[o] = aq; k4[o] = ak; v4[o] = av;
        sh[t*4 + o]            = aq;
        sh[INNERq + t*4 + o]   = ak;
        sh[2*INNERq + t*4 + o] = av;
    }
    *(float4*)&g_q[rowbase + t*4] = make_float4(q4[0], q4[1], q4[2], q4[3]);
    *(float4*)&g_k[rowbase + t*4] = make_float4(k4[0], k4[1], k4[2], k4[3]);
    *(float4*)&g_v[rowbase + t*4] = make_float4(v4[0], v4[1], v4[2], v4[3]);
    __syncthreads();

    int w = t >> 5, l = t & 31;
    #pragma unroll
    for (int g4 = 0; g4 < 4; g4++) {
        int g = w*4 + g4;
        int h = g & 7;
        const float* Wt = (g < 8 ? W_i : W_f) + h * 1536;
        float acc = 0.f;
        for (int idx = l*4; idx < 1536; idx += 128) {
            float4 sv = *(const float4*)&sh[idx];
            float4 wv = *(const float4*)&Wt[idx];
            acc += sv.x*wv.x + sv.y*wv.y + sv.z*wv.z + sv.w*wv.w;
        }
        #pragma unroll
        for (int o = 16; o; o >>= 1) acc += __shfl_xor_sync(0xffffffffu, acc, o);
        if (l == 0) {
            if (g < 8) g_ig[(size_t)(b*NHq + h) * Sq + s] = acc + b_i[h];
            else       g_fg[(size_t)(b*NHq + h) * Sq + s] = acc + b_f[h];
        }
    }
}

// ---------------- log-sigmoid + inclusive cumsum over S per (b,h) ----------------
__global__ __launch_bounds__(1024) void scan_kernel()
{
    int bh = blockIdx.x;
    int s = threadIdx.x;
    float x = g_fg[(size_t)bh * Sq + s];
    float lf = fminf(x, 0.f) - log1pf(expf(-fabsf(x)));
    __shared__ float sc[Sq];
    sc[s] = lf;
    __syncthreads();
    for (int off = 1; off < Sq; off <<= 1) {
        float tv = (s >= off) ? sc[s - off] : 0.f;
        __syncthreads();
        sc[s] += tv;
        __syncthreads();
    }
    g_lc[(size_t)bh * Sq + s] = sc[s];
}

// ---------------- attn v6 (R14): 32-row tiles, 1024 blocks, 128 threads ----------------
#define AST   68
#define QST   36
#define ATT_SMEM_FLOATS (64*QST + 2*64*AST + 32*AST + 2*64 + 5*32)
#define ATT_SMEM_BYTES  (ATT_SMEM_FLOATS*4)

__global__ __launch_bounds__(128) void attn_kernel(
    const float* __restrict__ norm_w, const float* __restrict__ skipw)
{
    extern __shared__ float sm[];
    float* Qt = sm;
    float* Kt = Qt + 64*QST;
    float* Vs = Kt + 64*AST;
    float* Pt = Vs + 64*AST;
    float* pm       = Pt + 32*AST;
    float* ej       = pm + 64;
    float* m_row    = ej + 64;
    float* sc_row   = m_row + 32;
    float* Ei_row   = sc_row + 32;
    float* ssum_row = Ei_row + 32;
    float* lci_row  = ssum_row + 32;

    int xblk = blockIdx.x;
    int r32 = 31 - (xblk >> 5);
    int bh = xblk & 31;
    int b = bh >> 3, h = bh & 7;
    int i0 = r32 * 32;
    int t = threadIdx.x;
    int tx = t & 15, ty = t >> 4;

    #pragma unroll
    for (int e4 = 0; e4 < 4; e4++) {
        int e = t + 128 * e4;
        int row = e >> 4, c4 = (e & 15) << 2;
        float4 qv = *(const float4*)&g_q[((size_t)(b*Sq + i0 + row)) * INNERq + h*DHq + c4];
        Qt[(c4+0)*QST + row] = qv.x;
        Qt[(c4+1)*QST + row] = qv.y;
        Qt[(c4+2)*QST + row] = qv.z;
        Qt[(c4+3)*QST + row] = qv.w;
    }
    if (t < 32) {
        lci_row[t]  = g_lc[(size_t)bh*Sq + i0 + t];
        m_row[t]    = -3.4e38f;
        ssum_row[t] = 0.f;
    }

    float acc[4][4];
    #pragma unroll
    for (int a = 0; a < 4; a++)
        #pragma unroll
        for (int d = 0; d < 4; d++) acc[a][d] = 0.f;

    int ntiles = (r32 >> 1) + 1;
    for (int jt = 0; jt < ntiles; jt++) {
        int j0 = jt * 64;
        __syncthreads();

        #pragma unroll
        for (int e4 = 0; e4 < 8; e4++) {
            int e = t + 128*e4;
            int row = e >> 4, c4 = (e & 15) << 2;
            size_t gb = ((size_t)(b*Sq + j0 + row)) * INNERq + h*DHq + c4;
            float4 kv = *(const float4*)&g_k[gb];
            float4 vv = *(const float4*)&g_v[gb];
            Kt[(c4+0)*AST + row] = kv.x*0.125f;
            Kt[(c4+1)*AST + row] = kv.y*0.125f;
            Kt[(c4+2)*AST + row] = kv.z*0.125f;
            Kt[(c4+3)*AST + row] = kv.w*0.125f;
            *(float4*)&Vs[row*AST + c4] = vv;
        }
        if (t < 32) {
            int l = t;
            size_t gbase = (size_t)bh*Sq + j0;
            float a0 = g_ig[gbase + l]      - g_lc[gbase + l];
            float a1 = g_ig[gbase + 32 + l] - g_lc[gbase + 32 + l];
            float p0 = a0;
            #pragma unroll
            for (int off = 1; off < 32; off <<= 1) {
                float u = __shfl_up_sync(0xffffffffu, p0, off);
                if (l >= off) p0 = fmaxf(p0, u);
            }
            float max0 = __shfl_sync(0xffffffffu, p0, 31);
            float p1 = a1;
            #pragma unroll
            for (int off = 1; off < 32; off <<= 1) {
                float u = __shfl_up_sync(0xffffffffu, p1, off);
                if (l >= off) p1 = fmaxf(p1, u);
            }
            p1 = fmaxf(p1, max0);
            float pmAll = __shfl_sync(0xffffffffu, p1, 31);
            pm[l]      = p0;
            pm[32 + l] = p1;
            ej[l]      = __expf(a0 - pmAll);
            ej[32 + l] = __expf(a1 - pmAll);
            __syncwarp();
            int r = l;
            int jm = i0 + r - j0 + 1;
            jm = jm > 64 ? 64 : jm;
            float mo = m_row[r];
            float rowmax = lci_row[r] + pm[jm-1];
            float mnew = fmaxf(mo, rowmax);
            float sc = __expf(mo - mnew);
            sc_row[r] = sc;
            Ei_row[r] = __expf(lci_row[r] + pmAll - mnew);
            m_row[r]  = mnew;
            ssum_row[r] *= sc;
        }
        __syncthreads();

        #pragma unroll
        for (int a = 0; a < 4; a++) {
            float sc = sc_row[4*ty + a];
            #pragma unroll
            for (int d = 0; d < 4; d++) acc[a][d] *= sc;
        }

        float s[4][4];
        #pragma unroll
        for (int a = 0; a < 4; a++)
            #pragma unroll
            for (int c = 0; c < 4; c++) s[a][c] = 0.f;
        #pragma unroll 8
        for (int kk = 0; kk < 64; kk++) {
            float4 aq = *(const float4*)&Qt[kk*QST + 4*ty];
            float4 bk = *(const float4*)&Kt[kk*AST + 4*tx];
            s[0][0] += aq.x*bk.x; s[0][1] += aq.x*bk.y; s[0][2] += aq.x*bk.z; s[0][3] += aq.x*bk.w;
            s[1][0] += aq.y*bk.x; s[1][1] += aq.y*bk.y; s[1][2] += aq.y*bk.z; s[1][3] += aq.y*bk.w;
            s[2][0] += aq.z*bk.x; s[2][1] += aq.z*bk.y; s[2][2] += aq.z*bk.z; s[2][3] += aq.z*bk.w;
            s[3][0] += aq.w*bk.x; s[3][1] += aq.w*bk.y; s[3][2] += aq.w*bk.z; s[3][3] += aq.w*bk.w;
        }
        {
            float e0 = ej[4*tx], e1 = ej[4*tx+1], e2 = ej[4*tx+2], e3 = ej[4*tx+3];
            bool diag = (jt == ntiles - 1);
            int jg = j0 + 4*tx;
            #pragma unroll
            for (int a = 0; a < 4; a++) {
                int rr = 4*ty + a;
                float Ei = Ei_row[rr];
                float p0 = s[a][0]*Ei*e0;
                float p1 = s[a][1]*Ei*e1;
                float p2 = s[a][2]*Ei*e2;
                float p3 = s[a][3]*Ei*e3;
                if (diag) {
                    int ig = i0 + rr;
                    if (jg     > ig) p0 = 0.f;
                    if (jg + 1 > ig) p1 = 0.f;
                    if (jg + 2 > ig) p2 = 0.f;
                    if (jg + 3 > ig) p3 = 0.f;
                }
                *(float4*)&Pt[rr*AST + 4*tx] = make_float4(p0, p1, p2, p3);
                float part = (p0 + p1) + (p2 + p3);
                part += __shfl_xor_sync(0xffffffffu, part, 1);
                part += __shfl_xor_sync(0xffffffffu, part, 2);
                part += __shfl_xor_sync(0xffffffffu, part, 4);
                part += __shfl_xor_sync(0xffffffffu, part, 8);
                if (tx == 0) ssum_row[rr] += part;
            }
        }
        __syncthreads();

        #pragma unroll 4
        for (int jj = 0; jj < 64; jj += 4) {
            float4 pa0 = *(const float4*)&Pt[(4*ty+0)*AST + jj];
            float4 pa1 = *(const float4*)&Pt[(4*ty+1)*AST + jj];
            float4 pa2 = *(const float4*)&Pt[(4*ty+2)*AST + jj];
            float4 pa3 = *(const float4*)&Pt[(4*ty+3)*AST + jj];
            float4 vb0 = *(const float4*)&Vs[(jj+0)*AST + 4*tx];
            float4 vb1 = *(const float4*)&Vs[(jj+1)*AST + 4*tx];
            float4 vb2 = *(const float4*)&Vs[(jj+2)*AST + 4*tx];
            float4 vb3 = *(const float4*)&Vs[(jj+3)*AST + 4*tx];
            acc[0][0] += pa0.x*vb0.x + pa0.y*vb1.x + pa0.z*vb2.x + pa0.w*vb3.x;
            acc[0][1] += pa0.x*vb0.y + pa0.y*vb1.y + pa0.z*vb2.y + pa0.w*vb3.y;
            acc[0][2] += pa0.x*vb0.z + pa0.y*vb1.z + pa0.z*vb2.z + pa0.w*vb3.z;
            acc[0][3] += pa0.x*vb0.w + pa0.y*vb1.w + pa0.z*vb2.w + pa0.w*vb3.w;
            acc[1][0] += pa1.x*vb0.x + pa1.y*vb1.x + pa1.z*vb2.x + pa1.w*vb3.x;
            acc[1][1] += pa1.x*vb0.y + pa1.y*vb1.y + pa1.z*vb2.y + pa1.w*vb3.y;
            acc[1][2] += pa1.x*vb0.z + pa1.y*vb1.z + pa1.z*vb2.z + pa1.w*vb3.z;
            acc[1][3] += pa1.x*vb0.w + pa1.y*vb1.w + pa1.z*vb2.w + pa1.w*vb3.w;
            acc[2][0] += pa2.x*vb0.x + pa2.y*vb1.x + pa2.z*vb2.x + pa2.w*vb3.x;
            acc[2][1] += pa2.x*vb0.y + pa2.y*vb1.y + pa2.z*vb2.y + pa2.w*vb3.y;
            acc[2][2] += pa2.x*vb0.z + pa2.y*vb1.z + pa2.z*vb2.z + pa2.w*vb3.z;
            acc[2][3] += pa2.x*vb0.w + pa2.y*vb1.w + pa2.z*vb2.w + pa2.w*vb3.w;
            acc[3][0] += pa3.x*vb0.x + pa3.y*vb1.x + pa3.z*vb2.x + pa3.w*vb3.x;
            acc[3][1] += pa3.x*vb0.y + pa3.y*vb1.y + pa3.z*vb2.y + pa3.w*vb3.y;
            acc[3][2] += pa3.x*vb0.z + pa3.y*vb1.z + pa3.z*vb2.z + pa3.w*vb3.z;
            acc[3][3] += pa3.x*vb0.w + pa3.y*vb1.w + pa3.z*vb2.w + pa3.w*vb3.w;
        }
    }

    __syncthreads();
    #pragma unroll
    for (int a = 0; a < 4; a++)
        *(float4*)&Vs[(4*ty + a)*AST + 4*tx] =
            make_float4(acc[a][0], acc[a][1], acc[a][2], acc[a][3]);
    __syncthreads();

    {
        int row = t >> 2, qd = t & 3;
        int i = i0 + row;
        float m    = m_row[row];
        float ssum = ssum_row[row];
        float denom = fmaxf(fabsf(ssum), __expf(-m)) + 1e-6f;
        float inv = 1.f / denom;
        float o[16];
        #pragma unroll
        for (int k4 = 0; k4 < 4; k4++) {
            float4 v = *(const float4*)&Vs[row*AST + qd*16 + k4*4];
            o[k4*4+0] = v.x*inv; o[k4*4+1] = v.y*inv; o[k4*4+2] = v.z*inv; o[k4*4+3] = v.w*inv;
        }
        float mean = 0.f;
        #pragma unroll
        for (int d = 0; d < 16; d++) mean += o[d];
        mean += __shfl_xor_sync(0xffffffffu, mean, 1);
        mean += __shfl_xor_sync(0xffffffffu, mean, 2);
        mean *= (1.f / 64.f);
        float var = 0.f;
        #pragma unroll
        for (int d = 0; d < 16; d++) { float df = o[d] - mean; var += df * df; }
        var += __shfl_xor_sync(0xffffffffu, var, 1);
        var += __shfl_xor_sync(0xffffffffu, var, 2);
        var *= (1.f / 64.f);
        float rstd = rsqrtf(var + 1e-5f);
        size_t obase = ((size_t)(b*Sq + i)) * INNERq + h*DHq + qd*16;
        #pragma unroll
        for (int d = 0; d < 16; d++) {
            int c = h*DHq + qd*16 + d;
            float hn  = (o[d] - mean) * rstd * norm_w[c];
            float za  = g_z[obase + d];
            float sil = za / (1.f + __expf(-za));
            g_h[obase + d] = (hn + skipw[c] * g_xa[obase + d]) * sil;
        }
    }
}

// ---------------- launch ----------------
extern "C" void kernel_launch(void* const* d_in, const int* in_sizes, int n_in,
                              void* d_out, int out_size)
{
    const float* x      = (const float*)d_in[0];
    const float* W_up   = (const float*)d_in[1];
    const float* conv_w = (const float*)d_in[2];
    const float* conv_b = (const float*)d_in[3];
    const float* Wq     = (const float*)d_in[4];
    const float* Wk     = (const float*)d_in[5];
    const float* Wv     = (const float*)d_in[6];
    const float* W_i    = (const float*)d_in[7];
    const float* b_i    = (const float*)d_in[8];
    const float* W_f    = (const float*)d_in[9];
    const float* b_f    = (const float*)d_in[10];
    const float* norm_w = (const float*)d_in[11];
    const float* skipw  = (const float*)d_in[12];
    const float* W_down = (const float*)d_in[13];
    float* out = (float*)d_out;

    cudaFuncSetAttribute(attn_kernel,
                         cudaFuncAttributeMaxDynamicSharedMemorySize, ATT_SMEM_BYTES);

    gemm_up<<<dim3(8, 32), 256>>>(x, W_up);
    fused_conv_qkv_gates<<<Bq*Sq, 128>>>(conv_w, conv_b, Wq, Wk, Wv, W_i, b_i, W_f, b_f);
    scan_kernel<<<Bq*NHq, 1024>>>();
    attn_kernel<<<1024, 128, ATT_SMEM_BYTES>>>(norm_w, skipw);
    gemm_down<<<dim3(4, 32), 256>>>(W_down, out);
}